// round 1
// baseline (speedup 1.0000x reference)
#include <cuda_runtime.h>

#define NE   2048
#define NH   16
#define NKV  4
#define HD   128
#define SEQ  2048
#define BATCH 2

// -------- device scratch (no allocations allowed in kernel_launch) --------
__device__ float g_q[(size_t)BATCH * NH  * SEQ * HD];   // (b,h,s,d)
__device__ float g_k[(size_t)BATCH * NKV * SEQ * HD];   // (b,kvh,s,d), rope applied
__device__ float g_v[(size_t)BATCH * NKV * SEQ * HD];   // (b,kvh,s,d)
__device__ float g_y[(size_t)BATCH * SEQ * NE];         // attention out, (b,s,e)

// log2(10000)/128
#define ROPE_L2 0.10381025296522976f

// ==========================================================================
// Kernel 1: fused QKV projection + RoPE epilogue.
// C[m,n] = sum_k x[m,k] * W[n,k],  n in [0,3072) = [Wq | Wk | Wv]
// tile 128(M) x 64(N), K-step 16, 256 threads, 8x4 micro-tile.
// ==========================================================================
__global__ __launch_bounds__(256)
void qkv_rope_kernel(const float* __restrict__ x,
                     const float* __restrict__ Wq,
                     const float* __restrict__ Wk,
                     const float* __restrict__ Wv,
                     const int*   __restrict__ pos_ids)
{
    __shared__ float As[128 * 17];
    __shared__ float Bs[64 * 17];

    const int tid = threadIdx.x;
    const int tx  = tid & 15;          // 16 col-groups * 4 cols
    const int ty  = tid >> 4;          // 16 row-groups * 8 rows
    const int bn  = blockIdx.x * 64;   // 0..3071
    const int bm  = blockIdx.y * 128;  // 0..4095

    const float* W;
    int nloc;
    if (bn < NH * HD)            { W = Wq; nloc = bn; }
    else if (bn < NH*HD + NKV*HD){ W = Wk; nloc = bn - NH*HD; }
    else                         { W = Wv; nloc = bn - NH*HD - NKV*HD; }

    float acc[8][4];
#pragma unroll
    for (int i = 0; i < 8; i++)
#pragma unroll
        for (int j = 0; j < 4; j++) acc[i][j] = 0.f;

    const float* Abase = x + (size_t)bm * NE;
    const float* Bbase = W + (size_t)nloc * NE;

    const int lr = tid >> 2;    // 0..63
    const int lq = tid & 3;     // quad within 16-wide k slab

    for (int k0 = 0; k0 < NE; k0 += 16) {
#pragma unroll
        for (int p = 0; p < 2; p++) {
            int r = lr + p * 64;
            float4 v = *(const float4*)(Abase + (size_t)r * NE + k0 + lq * 4);
            float* d = &As[r * 17 + lq * 4];
            d[0] = v.x; d[1] = v.y; d[2] = v.z; d[3] = v.w;
        }
        {
            float4 v = *(const float4*)(Bbase + (size_t)lr * NE + k0 + lq * 4);
            float* d = &Bs[lr * 17 + lq * 4];
            d[0] = v.x; d[1] = v.y; d[2] = v.z; d[3] = v.w;
        }
        __syncthreads();
#pragma unroll
        for (int kk = 0; kk < 16; kk++) {
            float a[8], b[4];
#pragma unroll
            for (int i = 0; i < 8; i++) a[i] = As[(ty * 8 + i) * 17 + kk];
#pragma unroll
            for (int j = 0; j < 4; j++) b[j] = Bs[(tx * 4 + j) * 17 + kk];
#pragma unroll
            for (int i = 0; i < 8; i++)
#pragma unroll
                for (int j = 0; j < 4; j++)
                    acc[i][j] = fmaf(a[i], b[j], acc[i][j]);
        }
        __syncthreads();
    }

    // ---------------- epilogue: RoPE + scatter to (b,h,s,d) ----------------
    const int n0 = bn + tx * 4;  // 4 consecutive out-cols, 4-aligned -> rope pairs complete
#pragma unroll
    for (int i = 0; i < 8; i++) {
        int m = bm + ty * 8 + i;
        int b = m >> 11;
        int s = m & (SEQ - 1);
        float v0 = acc[i][0], v1 = acc[i][1], v2 = acc[i][2], v3 = acc[i][3];

        if (n0 < NH * HD) {
            int h = n0 >> 7, d0 = n0 & 127;
            float pos = (float)pos_ids[s];
            float f0 = pos * exp2f(-(float)d0 * ROPE_L2);
            float f1 = pos * exp2f(-(float)(d0 + 2) * ROPE_L2);
            float s0, c0, s1, c1;
            sincosf(f0, &s0, &c0);
            sincosf(f1, &s1, &c1);
            float4 o;
            o.x = v0 * c0 - v1 * s0;
            o.y = v1 * c0 + v0 * s0;
            o.z = v2 * c1 - v3 * s1;
            o.w = v3 * c1 + v2 * s1;
            *(float4*)&g_q[(((size_t)(b * NH + h)) * SEQ + s) * HD + d0] = o;
        } else if (n0 < NH * HD + NKV * HD) {
            int nl = n0 - NH * HD;
            int h = nl >> 7, d0 = nl & 127;
            float pos = (float)pos_ids[s];
            float f0 = pos * exp2f(-(float)d0 * ROPE_L2);
            float f1 = pos * exp2f(-(float)(d0 + 2) * ROPE_L2);
            float s0, c0, s1, c1;
            sincosf(f0, &s0, &c0);
            sincosf(f1, &s1, &c1);
            float4 o;
            o.x = v0 * c0 - v1 * s0;
            o.y = v1 * c0 + v0 * s0;
            o.z = v2 * c1 - v3 * s1;
            o.w = v3 * c1 + v2 * s1;
            *(float4*)&g_k[(((size_t)(b * NKV + h)) * SEQ + s) * HD + d0] = o;
        } else {
            int nl = n0 - NH * HD - NKV * HD;
            int h = nl >> 7, d0 = nl & 127;
            float4 o = make_float4(v0, v1, v2, v3);
            *(float4*)&g_v[(((size_t)(b * NKV + h)) * SEQ + s) * HD + d0] = o;
        }
    }
}

// ==========================================================================
// Kernel 2: flash-style causal attention.
// One block per (b, h, q-tile of 64). 256 threads.
// Scores: 64x64 via 4x4 micro-tiles; PV: 4 rows x 8 cols per thread.
// Online softmax. K smem XOR-swizzled (by key/4) for LDS.128.
// ==========================================================================
__global__ __launch_bounds__(256)
void attn_kernel(const int* __restrict__ pos_ids)
{
    extern __shared__ float sm[];
    float* Qs = sm;                    // [64][128], pre-scaled by 1/sqrt(D)
    float* Ks = Qs + 64 * 128;         // [64][128], swizzled
    float* Vs = Ks + 64 * 128;         // [64][128], row-major
    float* Ps = Vs + 64 * 128;         // [64][65]

    const int tid = threadIdx.x;
    const int tx  = tid & 15;
    const int ty  = tid >> 4;
    const int qt  = blockIdx.x;
    const int bh  = blockIdx.y;
    const int b   = bh >> 4, h = bh & 15;
    const int kvh = h >> 2;
    const int q0  = qt * 64;

    const float* Qg = g_q + (((size_t)(b * NH + h)) * SEQ + q0) * HD;
    const float* Kg = g_k + ((size_t)(b * NKV + kvh)) * SEQ * HD;
    const float* Vg = g_v + ((size_t)(b * NKV + kvh)) * SEQ * HD;

    const float sc = 0.08838834764831845f;  // 1/sqrt(128)
    for (int t = tid; t < 64 * 32; t += 256) {
        int r = t >> 5, c4 = t & 31;
        float4 q = *(const float4*)(Qg + (size_t)r * HD + c4 * 4);
        q.x *= sc; q.y *= sc; q.z *= sc; q.w *= sc;
        *(float4*)&Qs[r * HD + c4 * 4] = q;
    }

    float m_i[4], l_i[4], acc[4][8];
#pragma unroll
    for (int i = 0; i < 4; i++) {
        m_i[i] = -1e30f; l_i[i] = 0.f;
#pragma unroll
        for (int c = 0; c < 8; c++) acc[i][c] = 0.f;
    }

    int posq[4];
#pragma unroll
    for (int i = 0; i < 4; i++) posq[i] = pos_ids[q0 + ty * 4 + i];

    const int sw = tx & 7;

    for (int kt = 0; kt <= qt; kt++) {
        const int k0 = kt * 64;
        __syncthreads();   // protect Qs/Ks/Vs/Ps from previous iteration readers
        for (int t = tid; t < 64 * 32; t += 256) {
            int r = t >> 5, c4 = t & 31;
            float4 kv = *(const float4*)(Kg + (size_t)(k0 + r) * HD + c4 * 4);
            int c4s = c4 ^ ((r >> 2) & 7);
            *(float4*)&Ks[r * HD + c4s * 4] = kv;
            float4 vv = *(const float4*)(Vg + (size_t)(k0 + r) * HD + c4 * 4);
            *(float4*)&Vs[r * HD + c4 * 4] = vv;
        }
        __syncthreads();

        // ---- scores S = Q @ K^T (4x4 per thread) ----
        float s4[4][4];
#pragma unroll
        for (int i = 0; i < 4; i++)
#pragma unroll
            for (int j = 0; j < 4; j++) s4[i][j] = 0.f;

#pragma unroll 8
        for (int d4 = 0; d4 < 32; d4++) {
            float4 a[4], bb[4];
#pragma unroll
            for (int i = 0; i < 4; i++)
                a[i] = *(const float4*)&Qs[(ty * 4 + i) * HD + d4 * 4];
#pragma unroll
            for (int j = 0; j < 4; j++)
                bb[j] = *(const float4*)&Ks[(tx * 4 + j) * HD + ((d4 ^ sw) << 2)];
#pragma unroll
            for (int i = 0; i < 4; i++)
#pragma unroll
                for (int j = 0; j < 4; j++) {
                    s4[i][j] = fmaf(a[i].x, bb[j].x, s4[i][j]);
                    s4[i][j] = fmaf(a[i].y, bb[j].y, s4[i][j]);
                    s4[i][j] = fmaf(a[i].z, bb[j].z, s4[i][j]);
                    s4[i][j] = fmaf(a[i].w, bb[j].w, s4[i][j]);
                }
        }

        // causal mask: only the diagonal tile can be partially masked
        if (kt == qt) {
#pragma unroll
            for (int i = 0; i < 4; i++)
#pragma unroll
                for (int j = 0; j < 4; j++)
                    if (k0 + tx * 4 + j > posq[i]) s4[i][j] = -1e30f;
        }

        // ---- online softmax (row stats replicated across the 16 tx lanes) ----
#pragma unroll
        for (int i = 0; i < 4; i++) {
            float rm = fmaxf(fmaxf(s4[i][0], s4[i][1]), fmaxf(s4[i][2], s4[i][3]));
#pragma unroll
            for (int o = 1; o < 16; o <<= 1)
                rm = fmaxf(rm, __shfl_xor_sync(0xffffffffu, rm, o));
            float mn = fmaxf(m_i[i], rm);
            float corr = __expf(m_i[i] - mn);
            m_i[i] = mn;
            float rs = 0.f;
#pragma unroll
            for (int j = 0; j < 4; j++) {
                float pv = __expf(s4[i][j] - mn);
                s4[i][j] = pv;
                rs += pv;
            }
#pragma unroll
            for (int o = 1; o < 16; o <<= 1)
                rs += __shfl_xor_sync(0xffffffffu, rs, o);
            l_i[i] = l_i[i] * corr + rs;
#pragma unroll
            for (int c = 0; c < 8; c++) acc[i][c] *= corr;
#pragma unroll
            for (int j = 0; j < 4; j++)
                Ps[(ty * 4 + i) * 65 + tx * 4 + j] = s4[i][j];
        }
        __syncthreads();

        // ---- O += P @ V (4 rows x 8 cols per thread) ----
#pragma unroll 4
        for (int kk = 0; kk < 64; kk++) {
            float4 v0 = *(const float4*)&Vs[kk * HD + tx * 8];
            float4 v1 = *(const float4*)&Vs[kk * HD + tx * 8 + 4];
#pragma unroll
            for (int i = 0; i < 4; i++) {
                float pr = Ps[(ty * 4 + i) * 65 + kk];
                acc[i][0] = fmaf(pr, v0.x, acc[i][0]);
                acc[i][1] = fmaf(pr, v0.y, acc[i][1]);
                acc[i][2] = fmaf(pr, v0.z, acc[i][2]);
                acc[i][3] = fmaf(pr, v0.w, acc[i][3]);
                acc[i][4] = fmaf(pr, v1.x, acc[i][4]);
                acc[i][5] = fmaf(pr, v1.y, acc[i][5]);
                acc[i][6] = fmaf(pr, v1.z, acc[i][6]);
                acc[i][7] = fmaf(pr, v1.w, acc[i][7]);
            }
        }
    }

    // ---- normalize + write to (b, s, h*128 + d) ----
#pragma unroll
    for (int i = 0; i < 4; i++) {
        float inv = 1.0f / l_i[i];
        int qg = q0 + ty * 4 + i;
        size_t off = ((size_t)b * SEQ + qg) * NE + h * HD + tx * 8;
        float4 o0 = make_float4(acc[i][0] * inv, acc[i][1] * inv,
                                acc[i][2] * inv, acc[i][3] * inv);
        float4 o1 = make_float4(acc[i][4] * inv, acc[i][5] * inv,
                                acc[i][6] * inv, acc[i][7] * inv);
        *(float4*)&g_y[off]     = o0;
        *(float4*)&g_y[off + 4] = o1;
    }
}

// ==========================================================================
// Kernel 3: output projection  out[m,n] = sum_k g_y[m,k] * Wo[n,k]
// same GEMM shape as kernel 1.
// ==========================================================================
__global__ __launch_bounds__(256)
void out_proj_kernel(const float* __restrict__ Wo, float* __restrict__ out)
{
    __shared__ float As[128 * 17];
    __shared__ float Bs[64 * 17];

    const int tid = threadIdx.x;
    const int tx  = tid & 15;
    const int ty  = tid >> 4;
    const int bn  = blockIdx.x * 64;
    const int bm  = blockIdx.y * 128;

    float acc[8][4];
#pragma unroll
    for (int i = 0; i < 8; i++)
#pragma unroll
        for (int j = 0; j < 4; j++) acc[i][j] = 0.f;

    const float* Abase = g_y + (size_t)bm * NE;
    const float* Bbase = Wo + (size_t)bn * NE;

    const int lr = tid >> 2;
    const int lq = tid & 3;

    for (int k0 = 0; k0 < NE; k0 += 16) {
#pragma unroll
        for (int p = 0; p < 2; p++) {
            int r = lr + p * 64;
            float4 v = *(const float4*)(Abase + (size_t)r * NE + k0 + lq * 4);
            float* d = &As[r * 17 + lq * 4];
            d[0] = v.x; d[1] = v.y; d[2] = v.z; d[3] = v.w;
        }
        {
            float4 v = *(const float4*)(Bbase + (size_t)lr * NE + k0 + lq * 4);
            float* d = &Bs[lr * 17 + lq * 4];
            d[0] = v.x; d[1] = v.y; d[2] = v.z; d[3] = v.w;
        }
        __syncthreads();
#pragma unroll
        for (int kk = 0; kk < 16; kk++) {
            float a[8], b[4];
#pragma unroll
            for (int i = 0; i < 8; i++) a[i] = As[(ty * 8 + i) * 17 + kk];
#pragma unroll
            for (int j = 0; j < 4; j++) b[j] = Bs[(tx * 4 + j) * 17 + kk];
#pragma unroll
            for (int i = 0; i < 8; i++)
#pragma unroll
                for (int j = 0; j < 4; j++)
                    acc[i][j] = fmaf(a[i], b[j], acc[i][j]);
        }
        __syncthreads();
    }

    const int n0 = bn + tx * 4;
#pragma unroll
    for (int i = 0; i < 8; i++) {
        int m = bm + ty * 8 + i;
        float4 o = make_float4(acc[i][0], acc[i][1], acc[i][2], acc[i][3]);
        *(float4*)&out[(size_t)m * NE + n0] = o;
    }
}

// ==========================================================================
extern "C" void kernel_launch(void* const* d_in, const int* in_sizes, int n_in,
                              void* d_out, int out_size)
{
    const float* x   = (const float*)d_in[0];
    const float* Wq  = (const float*)d_in[1];
    const float* Wk  = (const float*)d_in[2];
    const float* Wv  = (const float*)d_in[3];
    const float* Wo  = (const float*)d_in[4];
    const int*   pos = (const int*)d_in[5];
    float* out = (float*)d_out;

    dim3 blk(256);

    // 1) QKV + RoPE: N = 3072 (48 tiles of 64), M = 4096 (32 tiles of 128)
    dim3 g1(48, 32);
    qkv_rope_kernel<<<g1, blk>>>(x, Wq, Wk, Wv, pos);

    // 2) attention
    int smem = (64 * 128 * 3 + 64 * 65) * (int)sizeof(float);  // 114944 B
    cudaFuncSetAttribute(attn_kernel,
                         cudaFuncAttributeMaxDynamicSharedMemorySize, smem);
    dim3 g2(SEQ / 64, BATCH * NH);
    attn_kernel<<<g2, blk, smem>>>(pos);

    // 3) output projection: N = 2048 (32 tiles), M = 4096 (32 tiles)
    dim3 g3(32, 32);
    out_proj_kernel<<<g3, blk>>>(Wo, out);
}

// round 3
// speedup vs baseline: 1.6004x; 1.6004x over previous
#include <cuda_runtime.h>
#include <cuda_bf16.h>
#include <cstdint>

#define NE    2048
#define NH    16
#define NKV   4
#define HD    128
#define SEQ   2048
#define BATCH 2
#define MTOT  (BATCH * SEQ)                 // 4096
#define NQKV  (NH * HD + 2 * NKV * HD)      // 3072

// log2(10000)/128
#define ROPE_L2 0.10381025296522976f

// -------------------- device scratch --------------------
__device__ float g_q[(size_t)BATCH * NH  * SEQ * HD];
__device__ float g_k[(size_t)BATCH * NKV * SEQ * HD];
__device__ float g_v[(size_t)BATCH * NKV * SEQ * HD];
__device__ float g_y[(size_t)BATCH * SEQ * NE];
__device__ float2 g_rope[SEQ * 64];

__device__ __nv_bfloat16 g_xhi[(size_t)MTOT * NE];
__device__ __nv_bfloat16 g_xlo[(size_t)MTOT * NE];
__device__ __nv_bfloat16 g_whi[(size_t)(NQKV + NE) * NE];
__device__ __nv_bfloat16 g_wlo[(size_t)(NQKV + NE) * NE];
__device__ __nv_bfloat16 g_yhi[(size_t)MTOT * NE];
__device__ __nv_bfloat16 g_ylo[(size_t)MTOT * NE];

// -------------------- PTX helpers (plain-target only) --------------------
__device__ __forceinline__ uint32_t cvta_smem(const void* p) {
    uint32_t a;
    asm("{ .reg .u64 t; cvta.to.shared.u64 t, %1; cvt.u32.u64 %0, t; }"
        : "=r"(a) : "l"(p));
    return a;
}
__device__ __forceinline__ void cp16(uint32_t dst, const void* src) {
    asm volatile("cp.async.cg.shared.global [%0], [%1], 16;" :: "r"(dst), "l"(src));
}
__device__ __forceinline__ void cp_commit() {
    asm volatile("cp.async.commit_group;" ::: "memory");
}
template <int N>
__device__ __forceinline__ void cp_wait() {
    asm volatile("cp.async.wait_group %0;" :: "n"(N) : "memory");
}
__device__ __forceinline__ void ldsm4(uint32_t& r0, uint32_t& r1,
                                      uint32_t& r2, uint32_t& r3, uint32_t a) {
    asm volatile("ldmatrix.sync.aligned.m8n8.x4.shared.b16 {%0,%1,%2,%3}, [%4];"
                 : "=r"(r0), "=r"(r1), "=r"(r2), "=r"(r3) : "r"(a));
}
__device__ __forceinline__ void mma16816(float* c, const uint32_t* a,
                                         const uint32_t* b) {
    asm volatile(
        "mma.sync.aligned.m16n8k16.row.col.f32.bf16.bf16.f32 "
        "{%0,%1,%2,%3}, {%4,%5,%6,%7}, {%8,%9}, {%0,%1,%2,%3};"
        : "+f"(c[0]), "+f"(c[1]), "+f"(c[2]), "+f"(c[3])
        : "r"(a[0]), "r"(a[1]), "r"(a[2]), "r"(a[3]), "r"(b[0]), "r"(b[1]));
}

// -------------------- fp32 -> bf16 hi/lo splits --------------------
__device__ __forceinline__ void split4(float4 v, uint2& hi, uint2& lo) {
    __nv_bfloat16 hx = __float2bfloat16(v.x), hy = __float2bfloat16(v.y);
    __nv_bfloat16 hz = __float2bfloat16(v.z), hw = __float2bfloat16(v.w);
    __nv_bfloat16 lx = __float2bfloat16(v.x - __bfloat162float(hx));
    __nv_bfloat16 ly = __float2bfloat16(v.y - __bfloat162float(hy));
    __nv_bfloat16 lz = __float2bfloat16(v.z - __bfloat162float(hz));
    __nv_bfloat16 lw = __float2bfloat16(v.w - __bfloat162float(hw));
    __nv_bfloat162 h01; h01.x = hx; h01.y = hy;
    __nv_bfloat162 h23; h23.x = hz; h23.y = hw;
    __nv_bfloat162 l01; l01.x = lx; l01.y = ly;
    __nv_bfloat162 l23; l23.x = lz; l23.y = lw;
    hi = make_uint2(*(uint32_t*)&h01, *(uint32_t*)&h23);
    lo = make_uint2(*(uint32_t*)&l01, *(uint32_t*)&l23);
}

__global__ void split_w_kernel(const float* __restrict__ src, int base4, int n4) {
    int i = blockIdx.x * 256 + threadIdx.x;
    if (i >= n4) return;
    uint2 h, l;
    split4(((const float4*)src)[i], h, l);
    ((uint2*)g_whi)[base4 + i] = h;
    ((uint2*)g_wlo)[base4 + i] = l;
}
__global__ void split_x_kernel(const float* __restrict__ src, int n4) {
    int i = blockIdx.x * 256 + threadIdx.x;
    if (i >= n4) return;
    uint2 h, l;
    split4(((const float4*)src)[i], h, l);
    ((uint2*)g_xhi)[i] = h;
    ((uint2*)g_xlo)[i] = l;
}
__global__ void split_y_kernel(int n4) {
    int i = blockIdx.x * 256 + threadIdx.x;
    if (i >= n4) return;
    uint2 h, l;
    split4(((const float4*)g_y)[i], h, l);
    ((uint2*)g_yhi)[i] = h;
    ((uint2*)g_ylo)[i] = l;
}
__global__ void fill_rope_kernel(const int* __restrict__ pos_ids) {
    int idx = blockIdx.x * 256 + threadIdx.x;
    if (idx >= SEQ * 64) return;
    int s = idx >> 6, p = idx & 63;
    float pos = (float)pos_ids[s];
    float f = pos * exp2f(-(float)(2 * p) * ROPE_L2);
    float sn, cs;
    sincosf(f, &sn, &cs);
    g_rope[idx] = make_float2(cs, sn);
}

// ==========================================================================
// bf16-split tensor-core GEMM:  C[m,n] = sum_k A[m,k] * W[n,k]
// CTA tile 128x128, 512 threads (16 warps, 4x4), warp tile 32x32.
// K-chunk 32, 3-stage cp.async pipeline, rows padded to 80B for ldmatrix.
// MODE 0: A = x-split, epilogue RoPE + scatter to g_q/g_k/g_v
// MODE 1: A = y-split, epilogue plain store to outp
// ==========================================================================
#define KCH     32
#define NSTG    (NE / KCH)       // 64
#define ROWB    80               // bytes per padded row (64B data + 16B pad)
#define MATB    (128 * ROWB)     // 10240 per matrix tile
#define STGB    (4 * MATB)       // 40960 per stage: Ahi|Alo|Bhi|Blo
#define NPIPE   3

template <int MODE>
__global__ __launch_bounds__(512, 1)
void gemm_kernel(int browbase, float* __restrict__ outp)
{
    extern __shared__ char smem[];
    const uint32_t sb = cvta_smem(smem);
    const int tid  = threadIdx.x;
    const int wid  = tid >> 5, lane = tid & 31;
    const int wm   = (wid >> 2) * 32;        // warp m-offset in tile
    const int wn   = (wid & 3) * 32;         // warp n-offset in tile
    const int bn   = blockIdx.x * 128;
    const int bm   = blockIdx.y * 128;

    const __nv_bfloat16* Ahi = (MODE == 0) ? g_xhi : g_yhi;
    const __nv_bfloat16* Alo = (MODE == 0) ? g_xlo : g_ylo;

    float acc[2][4][4];
#pragma unroll
    for (int i = 0; i < 2; i++)
#pragma unroll
        for (int j = 0; j < 4; j++)
#pragma unroll
            for (int q = 0; q < 4; q++) acc[i][j][q] = 0.f;

    // per-thread load slots: one 16B chunk in each of Ahi/Alo/Bhi/Blo
    const int lr = tid >> 2;        // row 0..127
    const int lc = tid & 3;         // chunk 0..3
    const uint32_t ldst = (uint32_t)(lr * ROWB + lc * 16);
    const size_t gA = (size_t)(bm + lr) * NE + lc * 8;
    const size_t gB = (size_t)(browbase + bn + lr) * NE + lc * 8;

    // ldmatrix addresses (within a stage, as offsets)
    // A: row = wm + (lane&15), k8 = lane>>4
    const uint32_t aoff = (uint32_t)((wm + (lane & 15)) * ROWB + (lane >> 4) * 16);
    // B: n = wn + (lane&7) + ((lane>>4)<<3), k8 = (lane>>3)&1
    const uint32_t boff = (uint32_t)((wn + (lane & 7) + ((lane >> 4) << 3)) * ROWB
                                     + ((lane >> 3) & 1) * 16);

    auto issue = [&](int s) {
        const uint32_t st = sb + (s % NPIPE) * STGB;
        const size_t ko = (size_t)s * KCH;
        cp16(st + ldst,            Ahi + gA + ko);
        cp16(st + MATB + ldst,     Alo + gA + ko);
        cp16(st + 2 * MATB + ldst, g_whi + gB + ko);
        cp16(st + 3 * MATB + ldst, g_wlo + gB + ko);
        cp_commit();
    };

    issue(0);
    issue(1);

    for (int s = 0; s < NSTG; s++) {
        if (s + 2 < NSTG) { issue(s + 2); cp_wait<2>(); }
        else if (s + 1 < NSTG) cp_wait<1>();
        else cp_wait<0>();
        __syncthreads();

        const uint32_t st = sb + (s % NPIPE) * STGB;
#pragma unroll
        for (int t = 0; t < 2; t++) {
            uint32_t ah[2][4], al[2][4], bh[8], bl[8];
#pragma unroll
            for (int f = 0; f < 2; f++) {
                ldsm4(ah[f][0], ah[f][1], ah[f][2], ah[f][3],
                      st + aoff + f * 16 * ROWB + t * 32);
                ldsm4(al[f][0], al[f][1], al[f][2], al[f][3],
                      st + MATB + aoff + f * 16 * ROWB + t * 32);
            }
#pragma unroll
            for (int g = 0; g < 2; g++) {
                ldsm4(bh[g * 4 + 0], bh[g * 4 + 1], bh[g * 4 + 2], bh[g * 4 + 3],
                      st + 2 * MATB + boff + g * 16 * ROWB + t * 32);
                ldsm4(bl[g * 4 + 0], bl[g * 4 + 1], bl[g * 4 + 2], bl[g * 4 + 3],
                      st + 3 * MATB + boff + g * 16 * ROWB + t * 32);
            }
#pragma unroll
            for (int f = 0; f < 2; f++)
#pragma unroll
                for (int n = 0; n < 4; n++) {
                    mma16816(acc[f][n], ah[f], &bh[n * 2]);
                    mma16816(acc[f][n], ah[f], &bl[n * 2]);
                    mma16816(acc[f][n], al[f], &bh[n * 2]);
                }
        }
        __syncthreads();
    }

    // ---------------- epilogue: fragments -> global ----------------
    const int r0 = lane >> 2;
    const int c0 = (lane & 3) * 2;

    if (MODE == 1) {
#pragma unroll
        for (int f = 0; f < 2; f++)
#pragma unroll
            for (int n = 0; n < 4; n++) {
                int m = bm + wm + f * 16 + r0;
                int c = bn + wn + n * 8 + c0;
                *(float2*)&outp[(size_t)m * NE + c] =
                    make_float2(acc[f][n][0], acc[f][n][1]);
                *(float2*)&outp[(size_t)(m + 8) * NE + c] =
                    make_float2(acc[f][n][2], acc[f][n][3]);
            }
    } else {
        const int region = (bn < NH * HD) ? 0 : ((bn < NH * HD + NKV * HD) ? 1 : 2);
#pragma unroll
        for (int f = 0; f < 2; f++)
#pragma unroll
            for (int n = 0; n < 4; n++) {
                int nglob = bn + wn + n * 8 + c0;
#pragma unroll
                for (int half = 0; half < 2; half++) {
                    int m = bm + wm + f * 16 + r0 + half * 8;
                    int bb = m >> 11, s = m & (SEQ - 1);
                    float v0 = acc[f][n][half * 2 + 0];
                    float v1 = acc[f][n][half * 2 + 1];
                    if (region == 2) {
                        int nl = nglob - NH * HD - NKV * HD;
                        int h = nl >> 7, d0 = nl & 127;
                        *(float2*)&g_v[(((size_t)(bb * NKV + h)) * SEQ + s) * HD + d0]
                            = make_float2(v0, v1);
                    } else {
                        int nl = (region == 0) ? nglob : (nglob - NH * HD);
                        int h = nl >> 7, d0 = nl & 127;
                        float2 cs = g_rope[s * 64 + (d0 >> 1)];
                        float2 o = make_float2(v0 * cs.x - v1 * cs.y,
                                               v1 * cs.x + v0 * cs.y);
                        if (region == 0)
                            *(float2*)&g_q[(((size_t)(bb * NH + h)) * SEQ + s) * HD + d0] = o;
                        else
                            *(float2*)&g_k[(((size_t)(bb * NKV + h)) * SEQ + s) * HD + d0] = o;
                    }
                }
            }
    }
}

// ==========================================================================
// flash-style causal attention (fp32 SIMT) — unchanged
// ==========================================================================
__global__ __launch_bounds__(256)
void attn_kernel(const int* __restrict__ pos_ids)
{
    extern __shared__ float sm[];
    float* Qs = sm;
    float* Ks = Qs + 64 * 128;
    float* Vs = Ks + 64 * 128;
    float* Ps = Vs + 64 * 128;

    const int tid = threadIdx.x;
    const int tx  = tid & 15;
    const int ty  = tid >> 4;
    const int qt  = blockIdx.x;
    const int bh  = blockIdx.y;
    const int b   = bh >> 4, h = bh & 15;
    const int kvh = h >> 2;
    const int q0  = qt * 64;

    const float* Qg = g_q + (((size_t)(b * NH + h)) * SEQ + q0) * HD;
    const float* Kg = g_k + ((size_t)(b * NKV + kvh)) * SEQ * HD;
    const float* Vg = g_v + ((size_t)(b * NKV + kvh)) * SEQ * HD;

    const float sc = 0.08838834764831845f;
    for (int t = tid; t < 64 * 32; t += 256) {
        int r = t >> 5, c4 = t & 31;
        float4 q = *(const float4*)(Qg + (size_t)r * HD + c4 * 4);
        q.x *= sc; q.y *= sc; q.z *= sc; q.w *= sc;
        *(float4*)&Qs[r * HD + c4 * 4] = q;
    }

    float m_i[4], l_i[4], acc[4][8];
#pragma unroll
    for (int i = 0; i < 4; i++) {
        m_i[i] = -1e30f; l_i[i] = 0.f;
#pragma unroll
        for (int c = 0; c < 8; c++) acc[i][c] = 0.f;
    }

    int posq[4];
#pragma unroll
    for (int i = 0; i < 4; i++) posq[i] = pos_ids[q0 + ty * 4 + i];

    const int sw = tx & 7;

    for (int kt = 0; kt <= qt; kt++) {
        const int k0 = kt * 64;
        __syncthreads();
        for (int t = tid; t < 64 * 32; t += 256) {
            int r = t >> 5, c4 = t & 31;
            float4 kv = *(const float4*)(Kg + (size_t)(k0 + r) * HD + c4 * 4);
            int c4s = c4 ^ ((r >> 2) & 7);
            *(float4*)&Ks[r * HD + c4s * 4] = kv;
            float4 vv = *(const float4*)(Vg + (size_t)(k0 + r) * HD + c4 * 4);
            *(float4*)&Vs[r * HD + c4 * 4] = vv;
        }
        __syncthreads();

        float s4[4][4];
#pragma unroll
        for (int i = 0; i < 4; i++)
#pragma unroll
            for (int j = 0; j < 4; j++) s4[i][j] = 0.f;

#pragma unroll 8
        for (int d4 = 0; d4 < 32; d4++) {
            float4 a[4], bb[4];
#pragma unroll
            for (int i = 0; i < 4; i++)
                a[i] = *(const float4*)&Qs[(ty * 4 + i) * HD + d4 * 4];
#pragma unroll
            for (int j = 0; j < 4; j++)
                bb[j] = *(const float4*)&Ks[(tx * 4 + j) * HD + ((d4 ^ sw) << 2)];
#pragma unroll
            for (int i = 0; i < 4; i++)
#pragma unroll
                for (int j = 0; j < 4; j++) {
                    s4[i][j] = fmaf(a[i].x, bb[j].x, s4[i][j]);
                    s4[i][j] = fmaf(a[i].y, bb[j].y, s4[i][j]);
                    s4[i][j] = fmaf(a[i].z, bb[j].z, s4[i][j]);
                    s4[i][j] = fmaf(a[i].w, bb[j].w, s4[i][j]);
                }
        }

        if (kt == qt) {
#pragma unroll
            for (int i = 0; i < 4; i++)
#pragma unroll
                for (int j = 0; j < 4; j++)
                    if (k0 + tx * 4 + j > posq[i]) s4[i][j] = -1e30f;
        }

#pragma unroll
        for (int i = 0; i < 4; i++) {
            float rm = fmaxf(fmaxf(s4[i][0], s4[i][1]), fmaxf(s4[i][2], s4[i][3]));
#pragma unroll
            for (int o = 1; o < 16; o <<= 1)
                rm = fmaxf(rm, __shfl_xor_sync(0xffffffffu, rm, o));
            float mn = fmaxf(m_i[i], rm);
            float corr = __expf(m_i[i] - mn);
            m_i[i] = mn;
            float rs = 0.f;
#pragma unroll
            for (int j = 0; j < 4; j++) {
                float pv = __expf(s4[i][j] - mn);
                s4[i][j] = pv;
                rs += pv;
            }
#pragma unroll
            for (int o = 1; o < 16; o <<= 1)
                rs += __shfl_xor_sync(0xffffffffu, rs, o);
            l_i[i] = l_i[i] * corr + rs;
#pragma unroll
            for (int c = 0; c < 8; c++) acc[i][c] *= corr;
#pragma unroll
            for (int j = 0; j < 4; j++)
                Ps[(ty * 4 + i) * 65 + tx * 4 + j] = s4[i][j];
        }
        __syncthreads();

#pragma unroll 4
        for (int kk = 0; kk < 64; kk++) {
            float4 v0 = *(const float4*)&Vs[kk * HD + tx * 8];
            float4 v1 = *(const float4*)&Vs[kk * HD + tx * 8 + 4];
#pragma unroll
            for (int i = 0; i < 4; i++) {
                float pr = Ps[(ty * 4 + i) * 65 + kk];
                acc[i][0] = fmaf(pr, v0.x, acc[i][0]);
                acc[i][1] = fmaf(pr, v0.y, acc[i][1]);
                acc[i][2] = fmaf(pr, v0.z, acc[i][2]);
                acc[i][3] = fmaf(pr, v0.w, acc[i][3]);
                acc[i][4] = fmaf(pr, v1.x, acc[i][4]);
                acc[i][5] = fmaf(pr, v1.y, acc[i][5]);
                acc[i][6] = fmaf(pr, v1.z, acc[i][6]);
                acc[i][7] = fmaf(pr, v1.w, acc[i][7]);
            }
        }
    }

#pragma unroll
    for (int i = 0; i < 4; i++) {
        float inv = 1.0f / l_i[i];
        int qg = q0 + ty * 4 + i;
        size_t off = ((size_t)b * SEQ + qg) * NE + h * HD + tx * 8;
        float4 o0 = make_float4(acc[i][0] * inv, acc[i][1] * inv,
                                acc[i][2] * inv, acc[i][3] * inv);
        float4 o1 = make_float4(acc[i][4] * inv, acc[i][5] * inv,
                                acc[i][6] * inv, acc[i][7] * inv);
        *(float4*)&g_y[off]     = o0;
        *(float4*)&g_y[off + 4] = o1;
    }
}

// ==========================================================================
extern "C" void kernel_launch(void* const* d_in, const int* in_sizes, int n_in,
                              void* d_out, int out_size)
{
    const float* x   = (const float*)d_in[0];
    const float* Wq  = (const float*)d_in[1];
    const float* Wk  = (const float*)d_in[2];
    const float* Wv  = (const float*)d_in[3];
    const float* Wo  = (const float*)d_in[4];
    const int*   pos = (const int*)d_in[5];
    float* out = (float*)d_out;

    fill_rope_kernel<<<(SEQ * 64 + 255) / 256, 256>>>(pos);

    {
        int n4x = MTOT * NE / 4;
        split_x_kernel<<<(n4x + 255) / 256, 256>>>(x, n4x);
        int n4q = NH * HD * NE / 4;
        int n4k = NKV * HD * NE / 4;
        split_w_kernel<<<(n4q + 255) / 256, 256>>>(Wq, 0, n4q);
        split_w_kernel<<<(n4k + 255) / 256, 256>>>(Wk, (NH * HD) * NE / 4, n4k);
        split_w_kernel<<<(n4k + 255) / 256, 256>>>(Wv, (NH * HD + NKV * HD) * NE / 4, n4k);
        split_w_kernel<<<(n4q + 255) / 256, 256>>>(Wo, NQKV * NE / 4, n4q);
    }

    const int gsmem = NPIPE * STGB;   // 122880
    cudaFuncSetAttribute(gemm_kernel<0>,
                         cudaFuncAttributeMaxDynamicSharedMemorySize, gsmem);
    cudaFuncSetAttribute(gemm_kernel<1>,
                         cudaFuncAttributeMaxDynamicSharedMemorySize, gsmem);

    // QKV projection: N = 3072 -> 24 tiles of 128; M = 4096 -> 32 tiles
    gemm_kernel<0><<<dim3(24, 32), 512, gsmem>>>(0, nullptr);

    // attention
    int asmem = (64 * 128 * 3 + 64 * 65) * (int)sizeof(float);
    cudaFuncSetAttribute(attn_kernel,
                         cudaFuncAttributeMaxDynamicSharedMemorySize, asmem);
    attn_kernel<<<dim3(SEQ / 64, BATCH * NH), 256, asmem>>>(pos);

    {
        int n4y = MTOT * NE / 4;
        split_y_kernel<<<(n4y + 255) / 256, 256>>>(n4y);
    }

    // output projection: N = 2048 -> 16 tiles; M = 4096 -> 32 tiles
    gemm_kernel<1><<<dim3(16, 32), 512, gsmem>>>(NQKV, out);
}

// round 4
// speedup vs baseline: 2.6944x; 1.6836x over previous
#include <cuda_runtime.h>
#include <cuda_bf16.h>
#include <cstdint>

#define NE    2048
#define NH    16
#define NKV   4
#define HD    128
#define SEQ   2048
#define BATCH 2
#define MTOT  (BATCH * SEQ)                 // 4096
#define NQKV  (NH * HD + 2 * NKV * HD)      // 3072

#define ROPE_L2 0.10381025296522976f
#define SC 0.08838834764831845f             // 1/sqrt(128)

// -------------------- device scratch --------------------
__device__ float2 g_rope[SEQ * 64];

__device__ __nv_bfloat16 g_xhi[(size_t)MTOT * NE];
__device__ __nv_bfloat16 g_xlo[(size_t)MTOT * NE];
__device__ __nv_bfloat16 g_whi[(size_t)(NQKV + NE) * NE];
__device__ __nv_bfloat16 g_wlo[(size_t)(NQKV + NE) * NE];
__device__ __nv_bfloat16 g_yhi[(size_t)MTOT * NE];
__device__ __nv_bfloat16 g_ylo[(size_t)MTOT * NE];

__device__ __nv_bfloat16 g_qhi[(size_t)BATCH * NH * SEQ * HD];
__device__ __nv_bfloat16 g_qlo[(size_t)BATCH * NH * SEQ * HD];
__device__ __nv_bfloat16 g_khi[(size_t)BATCH * NKV * SEQ * HD];
__device__ __nv_bfloat16 g_klo[(size_t)BATCH * NKV * SEQ * HD];
__device__ __nv_bfloat16 g_vhi[(size_t)BATCH * NKV * SEQ * HD];
__device__ __nv_bfloat16 g_vlo[(size_t)BATCH * NKV * SEQ * HD];

// -------------------- PTX helpers (plain-target only) --------------------
__device__ __forceinline__ uint32_t cvta_smem(const void* p) {
    uint32_t a;
    asm("{ .reg .u64 t; cvta.to.shared.u64 t, %1; cvt.u32.u64 %0, t; }"
        : "=r"(a) : "l"(p));
    return a;
}
__device__ __forceinline__ void cp16(uint32_t dst, const void* src) {
    asm volatile("cp.async.cg.shared.global [%0], [%1], 16;" :: "r"(dst), "l"(src));
}
__device__ __forceinline__ void cp_commit() {
    asm volatile("cp.async.commit_group;" ::: "memory");
}
template <int N>
__device__ __forceinline__ void cp_wait() {
    asm volatile("cp.async.wait_group %0;" :: "n"(N) : "memory");
}
__device__ __forceinline__ void ldsm4(uint32_t& r0, uint32_t& r1,
                                      uint32_t& r2, uint32_t& r3, uint32_t a) {
    asm volatile("ldmatrix.sync.aligned.m8n8.x4.shared.b16 {%0,%1,%2,%3}, [%4];"
                 : "=r"(r0), "=r"(r1), "=r"(r2), "=r"(r3) : "r"(a));
}
__device__ __forceinline__ void ldsm4t(uint32_t& r0, uint32_t& r1,
                                       uint32_t& r2, uint32_t& r3, uint32_t a) {
    asm volatile("ldmatrix.sync.aligned.m8n8.x4.trans.shared.b16 {%0,%1,%2,%3}, [%4];"
                 : "=r"(r0), "=r"(r1), "=r"(r2), "=r"(r3) : "r"(a));
}
__device__ __forceinline__ void mma16816(float* c, const uint32_t* a,
                                         const uint32_t* b) {
    asm volatile(
        "mma.sync.aligned.m16n8k16.row.col.f32.bf16.bf16.f32 "
        "{%0,%1,%2,%3}, {%4,%5,%6,%7}, {%8,%9}, {%0,%1,%2,%3};"
        : "+f"(c[0]), "+f"(c[1]), "+f"(c[2]), "+f"(c[3])
        : "r"(a[0]), "r"(a[1]), "r"(a[2]), "r"(a[3]), "r"(b[0]), "r"(b[1]));
}

// -------------------- fp32 -> bf16 hi/lo --------------------
__device__ __forceinline__ void pack_split(float a, float b,
                                           uint32_t& hi, uint32_t& lo) {
    __nv_bfloat162 h, l;
    h.x = __float2bfloat16(a); h.y = __float2bfloat16(b);
    l.x = __float2bfloat16(a - __bfloat162float(h.x));
    l.y = __float2bfloat16(b - __bfloat162float(h.y));
    hi = *(uint32_t*)&h; lo = *(uint32_t*)&l;
}
__device__ __forceinline__ void store_split(__nv_bfloat16* hi, __nv_bfloat16* lo,
                                            size_t off, float a, float b) {
    uint32_t h, l;
    pack_split(a, b, h, l);
    *(uint32_t*)&hi[off] = h;
    *(uint32_t*)&lo[off] = l;
}
__device__ __forceinline__ void split4(float4 v, uint2& hi, uint2& lo) {
    uint32_t h0, h1, l0, l1;
    pack_split(v.x, v.y, h0, l0);
    pack_split(v.z, v.w, h1, l1);
    hi = make_uint2(h0, h1);
    lo = make_uint2(l0, l1);
}

__global__ void split_w_kernel(const float* __restrict__ src, int base4, int n4) {
    int i = blockIdx.x * 256 + threadIdx.x;
    if (i >= n4) return;
    uint2 h, l;
    split4(((const float4*)src)[i], h, l);
    ((uint2*)g_whi)[base4 + i] = h;
    ((uint2*)g_wlo)[base4 + i] = l;
}
__global__ void split_x_kernel(const float* __restrict__ src, int n4) {
    int i = blockIdx.x * 256 + threadIdx.x;
    if (i >= n4) return;
    uint2 h, l;
    split4(((const float4*)src)[i], h, l);
    ((uint2*)g_xhi)[i] = h;
    ((uint2*)g_xlo)[i] = l;
}
__global__ void fill_rope_kernel(const int* __restrict__ pos_ids) {
    int idx = blockIdx.x * 256 + threadIdx.x;
    if (idx >= SEQ * 64) return;
    int s = idx >> 6, p = idx & 63;
    float pos = (float)pos_ids[s];
    float f = pos * exp2f(-(float)(2 * p) * ROPE_L2);
    float sn, cs;
    sincosf(f, &sn, &cs);
    g_rope[idx] = make_float2(cs, sn);
}

// ==========================================================================
// bf16-split tensor-core GEMM (as round 3), epilogue now writes bf16 hi/lo.
// MODE 0: A = x-split, RoPE + scatter to q/k/v hi/lo (Q pre-scaled by SC)
// MODE 1: A = y-split, fp32 store to outp
// ==========================================================================
#define KCH     32
#define NSTG    (NE / KCH)       // 64
#define ROWB    80
#define MATB    (128 * ROWB)     // 10240
#define STGB    (4 * MATB)       // 40960
#define NPIPE   3

template <int MODE>
__global__ __launch_bounds__(512, 1)
void gemm_kernel(int browbase, float* __restrict__ outp)
{
    extern __shared__ char smem[];
    const uint32_t sb = cvta_smem(smem);
    const int tid  = threadIdx.x;
    const int wid  = tid >> 5, lane = tid & 31;
    const int wm   = (wid >> 2) * 32;
    const int wn   = (wid & 3) * 32;
    const int bn   = blockIdx.x * 128;
    const int bm   = blockIdx.y * 128;

    const __nv_bfloat16* Ahi = (MODE == 0) ? g_xhi : g_yhi;
    const __nv_bfloat16* Alo = (MODE == 0) ? g_xlo : g_ylo;

    float acc[2][4][4];
#pragma unroll
    for (int i = 0; i < 2; i++)
#pragma unroll
        for (int j = 0; j < 4; j++)
#pragma unroll
            for (int q = 0; q < 4; q++) acc[i][j][q] = 0.f;

    const int lr = tid >> 2;
    const int lc = tid & 3;
    const uint32_t ldst = (uint32_t)(lr * ROWB + lc * 16);
    const size_t gA = (size_t)(bm + lr) * NE + lc * 8;
    const size_t gB = (size_t)(browbase + bn + lr) * NE + lc * 8;

    const uint32_t aoff = (uint32_t)((wm + (lane & 15)) * ROWB + (lane >> 4) * 16);
    const uint32_t boff = (uint32_t)((wn + (lane & 7) + ((lane >> 4) << 3)) * ROWB
                                     + ((lane >> 3) & 1) * 16);

    auto issue = [&](int s) {
        const uint32_t st = sb + (s % NPIPE) * STGB;
        const size_t ko = (size_t)s * KCH;
        cp16(st + ldst,            Ahi + gA + ko);
        cp16(st + MATB + ldst,     Alo + gA + ko);
        cp16(st + 2 * MATB + ldst, g_whi + gB + ko);
        cp16(st + 3 * MATB + ldst, g_wlo + gB + ko);
        cp_commit();
    };

    issue(0);
    issue(1);

    for (int s = 0; s < NSTG; s++) {
        if (s + 2 < NSTG) { issue(s + 2); cp_wait<2>(); }
        else if (s + 1 < NSTG) cp_wait<1>();
        else cp_wait<0>();
        __syncthreads();

        const uint32_t st = sb + (s % NPIPE) * STGB;
#pragma unroll
        for (int t = 0; t < 2; t++) {
            uint32_t ah[2][4], al[2][4], bh[8], bl[8];
#pragma unroll
            for (int f = 0; f < 2; f++) {
                ldsm4(ah[f][0], ah[f][1], ah[f][2], ah[f][3],
                      st + aoff + f * 16 * ROWB + t * 32);
                ldsm4(al[f][0], al[f][1], al[f][2], al[f][3],
                      st + MATB + aoff + f * 16 * ROWB + t * 32);
            }
#pragma unroll
            for (int g = 0; g < 2; g++) {
                ldsm4(bh[g * 4 + 0], bh[g * 4 + 1], bh[g * 4 + 2], bh[g * 4 + 3],
                      st + 2 * MATB + boff + g * 16 * ROWB + t * 32);
                ldsm4(bl[g * 4 + 0], bl[g * 4 + 1], bl[g * 4 + 2], bl[g * 4 + 3],
                      st + 3 * MATB + boff + g * 16 * ROWB + t * 32);
            }
#pragma unroll
            for (int f = 0; f < 2; f++)
#pragma unroll
                for (int n = 0; n < 4; n++) {
                    mma16816(acc[f][n], ah[f], &bh[n * 2]);
                    mma16816(acc[f][n], ah[f], &bl[n * 2]);
                    mma16816(acc[f][n], al[f], &bh[n * 2]);
                }
        }
        __syncthreads();
    }

    const int r0 = lane >> 2;
    const int c0 = (lane & 3) * 2;

    if (MODE == 1) {
#pragma unroll
        for (int f = 0; f < 2; f++)
#pragma unroll
            for (int n = 0; n < 4; n++) {
                int m = bm + wm + f * 16 + r0;
                int c = bn + wn + n * 8 + c0;
                *(float2*)&outp[(size_t)m * NE + c] =
                    make_float2(acc[f][n][0], acc[f][n][1]);
                *(float2*)&outp[(size_t)(m + 8) * NE + c] =
                    make_float2(acc[f][n][2], acc[f][n][3]);
            }
    } else {
        const int region = (bn < NH * HD) ? 0 : ((bn < NH * HD + NKV * HD) ? 1 : 2);
#pragma unroll
        for (int f = 0; f < 2; f++)
#pragma unroll
            for (int n = 0; n < 4; n++) {
                int nglob = bn + wn + n * 8 + c0;
#pragma unroll
                for (int half = 0; half < 2; half++) {
                    int m = bm + wm + f * 16 + r0 + half * 8;
                    int bb = m >> 11, s = m & (SEQ - 1);
                    float v0 = acc[f][n][half * 2 + 0];
                    float v1 = acc[f][n][half * 2 + 1];
                    if (region == 2) {
                        int nl = nglob - NH * HD - NKV * HD;
                        int h = nl >> 7, d0 = nl & 127;
                        size_t off = (((size_t)(bb * NKV + h)) * SEQ + s) * HD + d0;
                        store_split(g_vhi, g_vlo, off, v0, v1);
                    } else {
                        int nl = (region == 0) ? nglob : (nglob - NH * HD);
                        int h = nl >> 7, d0 = nl & 127;
                        float2 cs = g_rope[s * 64 + (d0 >> 1)];
                        float ox = v0 * cs.x - v1 * cs.y;
                        float oy = v1 * cs.x + v0 * cs.y;
                        if (region == 0) {
                            ox *= SC; oy *= SC;
                            size_t off = (((size_t)(bb * NH + h)) * SEQ + s) * HD + d0;
                            store_split(g_qhi, g_qlo, off, ox, oy);
                        } else {
                            size_t off = (((size_t)(bb * NKV + h)) * SEQ + s) * HD + d0;
                            store_split(g_khi, g_klo, off, ox, oy);
                        }
                    }
                }
            }
    }
}

// ==========================================================================
// Tensor-core flash attention, bf16-split operands, fp32 accum.
// CTA: 128 q-rows x (b,h). 8 warps, warp = 16 q-rows. K/V tiles of 64 keys,
// double-buffered cp.async. P re-split to bf16 in registers (C->A identity).
// ==========================================================================
#define AROW   272                      // 256B row + 16B pad
#define QTB    (128 * AROW)             // 34816 per Q matrix
#define KVM    (64 * AROW)              // 17408 per KV matrix
#define KVSTG  (4 * KVM)                // 69632 per stage
#define ATT_SMEM (2 * QTB + 2 * KVSTG)  // 208896

__global__ __launch_bounds__(256, 1)
void attn_kernel(const int* __restrict__ pos_ids)
{
    extern __shared__ char smem[];
    const uint32_t sb = cvta_smem(smem);
    const int tid = threadIdx.x;
    const int lane = tid & 31, wq = tid >> 5;
    const int qt = blockIdx.x, bh = blockIdx.y;
    const int b = bh >> 4, h = bh & 15, kvh = h >> 2;
    const int q0 = qt * 128;

    const size_t qbase = (((size_t)(b * NH + h)) * SEQ + q0) * HD;
    const size_t kvbase = ((size_t)(b * NKV + kvh)) * SEQ * HD;

    // ---- load Q (hi+lo) ----
#pragma unroll
    for (int it = 0; it < 16; it++) {
        int mat = it >> 3;
        int rem = (it & 7) * 256 + tid;        // 0..2047
        int row = rem >> 4, ch = rem & 15;
        const __nv_bfloat16* src = (mat ? g_qlo : g_qhi) + qbase
                                   + (size_t)row * HD + ch * 8;
        cp16(sb + mat * QTB + row * AROW + ch * 16, src);
    }
    cp_commit();

    const int nkt = 2 * qt + 2;

    auto issue_kv = [&](int kt) {
        const uint32_t st = sb + 2 * QTB + (kt & 1) * KVSTG;
        const int k0 = kt * 64;
#pragma unroll
        for (int it = 0; it < 16; it++) {
            int mat = it >> 2;
            int rem = (it & 3) * 256 + tid;    // 0..1023
            int row = rem >> 4, ch = rem & 15;
            const __nv_bfloat16* base =
                (mat == 0) ? g_khi : (mat == 1) ? g_klo
                : (mat == 2) ? g_vhi : g_vlo;
            cp16(st + mat * KVM + row * AROW + ch * 16,
                 base + kvbase + (size_t)(k0 + row) * HD + ch * 8);
        }
        cp_commit();
    };

    issue_kv(0);

    float m_lo = -1e30f, m_hi = -1e30f, l_lo = 0.f, l_hi = 0.f;
    float o_acc[16][4];
#pragma unroll
    for (int nt = 0; nt < 16; nt++)
#pragma unroll
        for (int j = 0; j < 4; j++) o_acc[nt][j] = 0.f;

    const int r_lo = lane >> 2;
    const int pq_lo = pos_ids[q0 + 16 * wq + r_lo];
    const int pq_hi = pos_ids[q0 + 16 * wq + r_lo + 8];

    const uint32_t q_a = sb + (16 * wq + (lane & 15)) * AROW + (lane >> 4) * 16;
    const uint32_t k_row = (lane & 7) + ((lane >> 4) << 3);
    const uint32_t k_cb  = ((lane >> 3) & 1) * 16;
    const uint32_t v_row = (lane & 7) + (((lane >> 3) & 1) << 3);
    const uint32_t v_cb  = (lane >> 4) * 16;

    for (int kt = 0; kt < nkt; kt++) {
        if (kt + 1 < nkt) { issue_kv(kt + 1); cp_wait<1>(); }
        else cp_wait<0>();
        __syncthreads();
        const uint32_t st = sb + 2 * QTB + (kt & 1) * KVSTG;
        const int k0 = kt * 64;

        // ---- S = Q K^T ----
        float s_acc[8][4];
#pragma unroll
        for (int nt = 0; nt < 8; nt++)
#pragma unroll
            for (int j = 0; j < 4; j++) s_acc[nt][j] = 0.f;

#pragma unroll
        for (int kc = 0; kc < 8; kc++) {
            uint32_t ah[4], al[4];
            ldsm4(ah[0], ah[1], ah[2], ah[3], q_a + kc * 32);
            ldsm4(al[0], al[1], al[2], al[3], q_a + QTB + kc * 32);
#pragma unroll
            for (int kp = 0; kp < 4; kp++) {
                uint32_t kh[4], kl[4];
                uint32_t ka = st + (16 * kp + k_row) * AROW + kc * 32 + k_cb;
                ldsm4(kh[0], kh[1], kh[2], kh[3], ka);
                ldsm4(kl[0], kl[1], kl[2], kl[3], ka + KVM);
                mma16816(s_acc[2 * kp],     ah, &kh[0]);
                mma16816(s_acc[2 * kp],     ah, &kl[0]);
                mma16816(s_acc[2 * kp],     al, &kh[0]);
                mma16816(s_acc[2 * kp + 1], ah, &kh[2]);
                mma16816(s_acc[2 * kp + 1], ah, &kl[2]);
                mma16816(s_acc[2 * kp + 1], al, &kh[2]);
            }
        }

        // ---- causal mask ----
        if (k0 + 63 > pq_lo) {
#pragma unroll
            for (int nt = 0; nt < 8; nt++) {
                int c = k0 + 8 * nt + 2 * (lane & 3);
                if (c     > pq_lo) s_acc[nt][0] = -1e30f;
                if (c + 1 > pq_lo) s_acc[nt][1] = -1e30f;
                if (c     > pq_hi) s_acc[nt][2] = -1e30f;
                if (c + 1 > pq_hi) s_acc[nt][3] = -1e30f;
            }
        }

        // ---- online softmax ----
        float rm_lo = -1e30f, rm_hi = -1e30f;
#pragma unroll
        for (int nt = 0; nt < 8; nt++) {
            rm_lo = fmaxf(rm_lo, fmaxf(s_acc[nt][0], s_acc[nt][1]));
            rm_hi = fmaxf(rm_hi, fmaxf(s_acc[nt][2], s_acc[nt][3]));
        }
#pragma unroll
        for (int o = 1; o < 4; o <<= 1) {
            rm_lo = fmaxf(rm_lo, __shfl_xor_sync(0xffffffffu, rm_lo, o));
            rm_hi = fmaxf(rm_hi, __shfl_xor_sync(0xffffffffu, rm_hi, o));
        }
        float nm_lo = fmaxf(m_lo, rm_lo), nm_hi = fmaxf(m_hi, rm_hi);
        float corr_lo = __expf(m_lo - nm_lo), corr_hi = __expf(m_hi - nm_hi);
        m_lo = nm_lo; m_hi = nm_hi;
        float rs_lo = 0.f, rs_hi = 0.f;
#pragma unroll
        for (int nt = 0; nt < 8; nt++) {
            s_acc[nt][0] = __expf(s_acc[nt][0] - nm_lo);
            s_acc[nt][1] = __expf(s_acc[nt][1] - nm_lo);
            s_acc[nt][2] = __expf(s_acc[nt][2] - nm_hi);
            s_acc[nt][3] = __expf(s_acc[nt][3] - nm_hi);
            rs_lo += s_acc[nt][0] + s_acc[nt][1];
            rs_hi += s_acc[nt][2] + s_acc[nt][3];
        }
#pragma unroll
        for (int o = 1; o < 4; o <<= 1) {
            rs_lo += __shfl_xor_sync(0xffffffffu, rs_lo, o);
            rs_hi += __shfl_xor_sync(0xffffffffu, rs_hi, o);
        }
        l_lo = l_lo * corr_lo + rs_lo;
        l_hi = l_hi * corr_hi + rs_hi;
#pragma unroll
        for (int nt = 0; nt < 16; nt++) {
            o_acc[nt][0] *= corr_lo; o_acc[nt][1] *= corr_lo;
            o_acc[nt][2] *= corr_hi; o_acc[nt][3] *= corr_hi;
        }

        // ---- O += P V ----
#pragma unroll
        for (int kc2 = 0; kc2 < 4; kc2++) {
            uint32_t phi[4], plo[4];
            pack_split(s_acc[2 * kc2][0],     s_acc[2 * kc2][1],     phi[0], plo[0]);
            pack_split(s_acc[2 * kc2][2],     s_acc[2 * kc2][3],     phi[1], plo[1]);
            pack_split(s_acc[2 * kc2 + 1][0], s_acc[2 * kc2 + 1][1], phi[2], plo[2]);
            pack_split(s_acc[2 * kc2 + 1][2], s_acc[2 * kc2 + 1][3], phi[3], plo[3]);
#pragma unroll
            for (int nd = 0; nd < 8; nd++) {
                uint32_t vh[4], vl[4];
                uint32_t va = st + 2 * KVM + (16 * kc2 + v_row) * AROW
                              + nd * 32 + v_cb;
                ldsm4t(vh[0], vh[1], vh[2], vh[3], va);
                ldsm4t(vl[0], vl[1], vl[2], vl[3], va + KVM);
                mma16816(o_acc[2 * nd],     phi, &vh[0]);
                mma16816(o_acc[2 * nd],     phi, &vl[0]);
                mma16816(o_acc[2 * nd],     plo, &vh[0]);
                mma16816(o_acc[2 * nd + 1], phi, &vh[2]);
                mma16816(o_acc[2 * nd + 1], phi, &vl[2]);
                mma16816(o_acc[2 * nd + 1], plo, &vh[2]);
            }
        }
        __syncthreads();   // all warps done with this stage before overwrite
    }

    // ---- epilogue: normalize + split-store y ----
    float inv_lo = 1.0f / l_lo, inv_hi = 1.0f / l_hi;
    int row_lo = q0 + 16 * wq + r_lo;
#pragma unroll
    for (int nt = 0; nt < 16; nt++) {
        int col = h * HD + 8 * nt + 2 * (lane & 3);
        size_t off_lo = (size_t)(b * SEQ + row_lo) * NE + col;
        size_t off_hi = (size_t)(b * SEQ + row_lo + 8) * NE + col;
        store_split(g_yhi, g_ylo, off_lo, o_acc[nt][0] * inv_lo, o_acc[nt][1] * inv_lo);
        store_split(g_yhi, g_ylo, off_hi, o_acc[nt][2] * inv_hi, o_acc[nt][3] * inv_hi);
    }
}

// ==========================================================================
extern "C" void kernel_launch(void* const* d_in, const int* in_sizes, int n_in,
                              void* d_out, int out_size)
{
    const float* x   = (const float*)d_in[0];
    const float* Wq  = (const float*)d_in[1];
    const float* Wk  = (const float*)d_in[2];
    const float* Wv  = (const float*)d_in[3];
    const float* Wo  = (const float*)d_in[4];
    const int*   pos = (const int*)d_in[5];
    float* out = (float*)d_out;

    fill_rope_kernel<<<(SEQ * 64 + 255) / 256, 256>>>(pos);

    {
        int n4x = MTOT * NE / 4;
        split_x_kernel<<<(n4x + 255) / 256, 256>>>(x, n4x);
        int n4q = NH * HD * NE / 4;
        int n4k = NKV * HD * NE / 4;
        split_w_kernel<<<(n4q + 255) / 256, 256>>>(Wq, 0, n4q);
        split_w_kernel<<<(n4k + 255) / 256, 256>>>(Wk, (NH * HD) * NE / 4, n4k);
        split_w_kernel<<<(n4k + 255) / 256, 256>>>(Wv, (NH * HD + NKV * HD) * NE / 4, n4k);
        split_w_kernel<<<(n4q + 255) / 256, 256>>>(Wo, NQKV * NE / 4, n4q);
    }

    const int gsmem = NPIPE * STGB;   // 122880
    cudaFuncSetAttribute(gemm_kernel<0>,
                         cudaFuncAttributeMaxDynamicSharedMemorySize, gsmem);
    cudaFuncSetAttribute(gemm_kernel<1>,
                         cudaFuncAttributeMaxDynamicSharedMemorySize, gsmem);

    // QKV projection
    gemm_kernel<0><<<dim3(24, 32), 512, gsmem>>>(0, nullptr);

    // attention (tensor-core)
    cudaFuncSetAttribute(attn_kernel,
                         cudaFuncAttributeMaxDynamicSharedMemorySize, ATT_SMEM);
    attn_kernel<<<dim3(SEQ / 128, BATCH * NH), 256, ATT_SMEM>>>(pos);

    // output projection
    gemm_kernel<1><<<dim3(16, 32), 512, gsmem>>>(NQKV, out);
}

// round 5
// speedup vs baseline: 2.7250x; 1.0114x over previous
#include <cuda_runtime.h>
#include <cuda_bf16.h>
#include <cstdint>

#define NE    2048
#define NH    16
#define NKV   4
#define HD    128
#define SEQ   2048
#define BATCH 2
#define MTOT  (BATCH * SEQ)                 // 4096
#define NQKV  (NH * HD + 2 * NKV * HD)      // 3072

#define ROPE_L2 0.10381025296522976f
#define SC 0.08838834764831845f             // 1/sqrt(128)

// -------------------- device scratch --------------------
__device__ float2 g_rope[SEQ * 64];

__device__ __nv_bfloat16 g_xhi[(size_t)MTOT * NE];
__device__ __nv_bfloat16 g_xlo[(size_t)MTOT * NE];
__device__ __nv_bfloat16 g_whi[(size_t)(NQKV + NE) * NE];
__device__ __nv_bfloat16 g_wlo[(size_t)(NQKV + NE) * NE];
__device__ __nv_bfloat16 g_yhi[(size_t)MTOT * NE];
__device__ __nv_bfloat16 g_ylo[(size_t)MTOT * NE];

__device__ __nv_bfloat16 g_qhi[(size_t)BATCH * NH * SEQ * HD];
__device__ __nv_bfloat16 g_qlo[(size_t)BATCH * NH * SEQ * HD];
__device__ __nv_bfloat16 g_khi[(size_t)BATCH * NKV * SEQ * HD];
__device__ __nv_bfloat16 g_klo[(size_t)BATCH * NKV * SEQ * HD];
__device__ __nv_bfloat16 g_vhi[(size_t)BATCH * NKV * SEQ * HD];
__device__ __nv_bfloat16 g_vlo[(size_t)BATCH * NKV * SEQ * HD];

// -------------------- PTX helpers (plain-target only) --------------------
__device__ __forceinline__ uint32_t cvta_smem(const void* p) {
    uint32_t a;
    asm("{ .reg .u64 t; cvta.to.shared.u64 t, %1; cvt.u32.u64 %0, t; }"
        : "=r"(a) : "l"(p));
    return a;
}
__device__ __forceinline__ void cp16(uint32_t dst, const void* src) {
    asm volatile("cp.async.cg.shared.global [%0], [%1], 16;" :: "r"(dst), "l"(src));
}
__device__ __forceinline__ void cp_commit() {
    asm volatile("cp.async.commit_group;" ::: "memory");
}
template <int N>
__device__ __forceinline__ void cp_wait() {
    asm volatile("cp.async.wait_group %0;" :: "n"(N) : "memory");
}
__device__ __forceinline__ void ldsm4(uint32_t& r0, uint32_t& r1,
                                      uint32_t& r2, uint32_t& r3, uint32_t a) {
    asm volatile("ldmatrix.sync.aligned.m8n8.x4.shared.b16 {%0,%1,%2,%3}, [%4];"
                 : "=r"(r0), "=r"(r1), "=r"(r2), "=r"(r3) : "r"(a));
}
__device__ __forceinline__ void ldsm4t(uint32_t& r0, uint32_t& r1,
                                       uint32_t& r2, uint32_t& r3, uint32_t a) {
    asm volatile("ldmatrix.sync.aligned.m8n8.x4.trans.shared.b16 {%0,%1,%2,%3}, [%4];"
                 : "=r"(r0), "=r"(r1), "=r"(r2), "=r"(r3) : "r"(a));
}
__device__ __forceinline__ void mma16816(float* c, const uint32_t* a,
                                         const uint32_t* b) {
    asm volatile(
        "mma.sync.aligned.m16n8k16.row.col.f32.bf16.bf16.f32 "
        "{%0,%1,%2,%3}, {%4,%5,%6,%7}, {%8,%9}, {%0,%1,%2,%3};"
        : "+f"(c[0]), "+f"(c[1]), "+f"(c[2]), "+f"(c[3])
        : "r"(a[0]), "r"(a[1]), "r"(a[2]), "r"(a[3]), "r"(b[0]), "r"(b[1]));
}

// -------------------- fp32 -> bf16 hi/lo --------------------
__device__ __forceinline__ void pack_split(float a, float b,
                                           uint32_t& hi, uint32_t& lo) {
    __nv_bfloat162 h, l;
    h.x = __float2bfloat16(a); h.y = __float2bfloat16(b);
    l.x = __float2bfloat16(a - __bfloat162float(h.x));
    l.y = __float2bfloat16(b - __bfloat162float(h.y));
    hi = *(uint32_t*)&h; lo = *(uint32_t*)&l;
}
__device__ __forceinline__ void store_split(__nv_bfloat16* hi, __nv_bfloat16* lo,
                                            size_t off, float a, float b) {
    uint32_t h, l;
    pack_split(a, b, h, l);
    *(uint32_t*)&hi[off] = h;
    *(uint32_t*)&lo[off] = l;
}
__device__ __forceinline__ void split4(float4 v, uint2& hi, uint2& lo) {
    uint32_t h0, h1, l0, l1;
    pack_split(v.x, v.y, h0, l0);
    pack_split(v.z, v.w, h1, l1);
    hi = make_uint2(h0, h1);
    lo = make_uint2(l0, l1);
}

__global__ void split_w_kernel(const float* __restrict__ src, int base4, int n4) {
    int i = blockIdx.x * 256 + threadIdx.x;
    if (i >= n4) return;
    uint2 h, l;
    split4(((const float4*)src)[i], h, l);
    ((uint2*)g_whi)[base4 + i] = h;
    ((uint2*)g_wlo)[base4 + i] = l;
}
__global__ void split_x_kernel(const float* __restrict__ src, int n4) {
    int i = blockIdx.x * 256 + threadIdx.x;
    if (i >= n4) return;
    uint2 h, l;
    split4(((const float4*)src)[i], h, l);
    ((uint2*)g_xhi)[i] = h;
    ((uint2*)g_xlo)[i] = l;
}
__global__ void fill_rope_kernel(const int* __restrict__ pos_ids) {
    int idx = blockIdx.x * 256 + threadIdx.x;
    if (idx >= SEQ * 64) return;
    int s = idx >> 6, p = idx & 63;
    float pos = (float)pos_ids[s];
    float f = pos * exp2f(-(float)(2 * p) * ROPE_L2);
    float sn, cs;
    sincosf(f, &sn, &cs);
    g_rope[idx] = make_float2(cs, sn);
}

// ==========================================================================
// bf16-split tensor-core GEMM:  C[m,n] = sum_k A[m,k] * W[n,k]
// CTA tile 128x128, 256 threads (8 warps, 2x4), warp tile 64x32.
// K-chunk 32, 3-stage cp.async pipeline, rows padded to 80B.
// MODE 0: A = x-split, RoPE + scatter to q/k/v hi/lo (Q pre-scaled by SC)
// MODE 1: A = y-split, fp32 store to outp
// ==========================================================================
#define KCH     32
#define NSTG    (NE / KCH)       // 64
#define ROWB    80
#define MATB    (128 * ROWB)     // 10240
#define STGB    (4 * MATB)       // 40960
#define NPIPE   3

template <int MODE>
__global__ __launch_bounds__(256, 1)
void gemm_kernel(int browbase, float* __restrict__ outp)
{
    extern __shared__ char smem[];
    const uint32_t sb = cvta_smem(smem);
    const int tid  = threadIdx.x;
    const int wid  = tid >> 5, lane = tid & 31;
    const int wm   = (wid >> 2) * 64;        // warp m-offset (0 or 64)
    const int wn   = (wid & 3) * 32;         // warp n-offset
    const int bn   = blockIdx.x * 128;
    const int bm   = blockIdx.y * 128;

    const __nv_bfloat16* Ahi = (MODE == 0) ? g_xhi : g_yhi;
    const __nv_bfloat16* Alo = (MODE == 0) ? g_xlo : g_ylo;

    float acc[4][4][4];
#pragma unroll
    for (int f = 0; f < 4; f++)
#pragma unroll
        for (int n = 0; n < 4; n++)
#pragma unroll
            for (int q = 0; q < 4; q++) acc[f][n][q] = 0.f;

    // loads: per matrix 512 chunks of 16B; 256 threads -> 2 each
    const int r0i = tid >> 2;              // rows tid/4 and +64
    const int c0i = tid & 3;               // 16B chunk
    const uint32_t ldst0 = (uint32_t)(r0i * ROWB + c0i * 16);
    const uint32_t ldst1 = (uint32_t)((r0i + 64) * ROWB + c0i * 16);
    const size_t gA0 = (size_t)(bm + r0i) * NE + c0i * 8;
    const size_t gA1 = (size_t)(bm + r0i + 64) * NE + c0i * 8;
    const size_t gB0 = (size_t)(browbase + bn + r0i) * NE + c0i * 8;
    const size_t gB1 = (size_t)(browbase + bn + r0i + 64) * NE + c0i * 8;

    const uint32_t aoff = (uint32_t)((wm + (lane & 15)) * ROWB + (lane >> 4) * 16);
    const uint32_t boff = (uint32_t)((wn + (lane & 7) + ((lane >> 4) << 3)) * ROWB
                                     + ((lane >> 3) & 1) * 16);

    auto issue = [&](int s) {
        const uint32_t st = sb + (s % NPIPE) * STGB;
        const size_t ko = (size_t)s * KCH;
        cp16(st + ldst0,            Ahi + gA0 + ko);
        cp16(st + ldst1,            Ahi + gA1 + ko);
        cp16(st + MATB + ldst0,     Alo + gA0 + ko);
        cp16(st + MATB + ldst1,     Alo + gA1 + ko);
        cp16(st + 2 * MATB + ldst0, g_whi + gB0 + ko);
        cp16(st + 2 * MATB + ldst1, g_whi + gB1 + ko);
        cp16(st + 3 * MATB + ldst0, g_wlo + gB0 + ko);
        cp16(st + 3 * MATB + ldst1, g_wlo + gB1 + ko);
        cp_commit();
    };

    issue(0);
    issue(1);

    for (int s = 0; s < NSTG; s++) {
        if (s + 2 < NSTG) { issue(s + 2); cp_wait<2>(); }
        else if (s + 1 < NSTG) cp_wait<1>();
        else cp_wait<0>();
        __syncthreads();

        const uint32_t st = sb + (s % NPIPE) * STGB;
#pragma unroll
        for (int t = 0; t < 2; t++) {
            uint32_t bh[8], bl[8];
#pragma unroll
            for (int g = 0; g < 2; g++) {
                ldsm4(bh[g * 4 + 0], bh[g * 4 + 1], bh[g * 4 + 2], bh[g * 4 + 3],
                      st + 2 * MATB + boff + g * 16 * ROWB + t * 32);
                ldsm4(bl[g * 4 + 0], bl[g * 4 + 1], bl[g * 4 + 2], bl[g * 4 + 3],
                      st + 3 * MATB + boff + g * 16 * ROWB + t * 32);
            }
#pragma unroll
            for (int f = 0; f < 4; f++) {
                uint32_t ah[4], al[4];
                ldsm4(ah[0], ah[1], ah[2], ah[3],
                      st + aoff + f * 16 * ROWB + t * 32);
                ldsm4(al[0], al[1], al[2], al[3],
                      st + MATB + aoff + f * 16 * ROWB + t * 32);
#pragma unroll
                for (int n = 0; n < 4; n++) {
                    mma16816(acc[f][n], ah, &bh[n * 2]);
                    mma16816(acc[f][n], ah, &bl[n * 2]);
                    mma16816(acc[f][n], al, &bh[n * 2]);
                }
            }
        }
        __syncthreads();
    }

    const int r0 = lane >> 2;
    const int c0 = (lane & 3) * 2;

    if (MODE == 1) {
#pragma unroll
        for (int f = 0; f < 4; f++)
#pragma unroll
            for (int n = 0; n < 4; n++) {
                int m = bm + wm + f * 16 + r0;
                int c = bn + wn + n * 8 + c0;
                *(float2*)&outp[(size_t)m * NE + c] =
                    make_float2(acc[f][n][0], acc[f][n][1]);
                *(float2*)&outp[(size_t)(m + 8) * NE + c] =
                    make_float2(acc[f][n][2], acc[f][n][3]);
            }
    } else {
        const int region = (bn < NH * HD) ? 0 : ((bn < NH * HD + NKV * HD) ? 1 : 2);
#pragma unroll
        for (int f = 0; f < 4; f++)
#pragma unroll
            for (int n = 0; n < 4; n++) {
                int nglob = bn + wn + n * 8 + c0;
#pragma unroll
                for (int half = 0; half < 2; half++) {
                    int m = bm + wm + f * 16 + r0 + half * 8;
                    int bb = m >> 11, s = m & (SEQ - 1);
                    float v0 = acc[f][n][half * 2 + 0];
                    float v1 = acc[f][n][half * 2 + 1];
                    if (region == 2) {
                        int nl = nglob - NH * HD - NKV * HD;
                        int h = nl >> 7, d0 = nl & 127;
                        size_t off = (((size_t)(bb * NKV + h)) * SEQ + s) * HD + d0;
                        store_split(g_vhi, g_vlo, off, v0, v1);
                    } else {
                        int nl = (region == 0) ? nglob : (nglob - NH * HD);
                        int h = nl >> 7, d0 = nl & 127;
                        float2 cs = g_rope[s * 64 + (d0 >> 1)];
                        float ox = v0 * cs.x - v1 * cs.y;
                        float oy = v1 * cs.x + v0 * cs.y;
                        if (region == 0) {
                            ox *= SC; oy *= SC;
                            size_t off = (((size_t)(bb * NH + h)) * SEQ + s) * HD + d0;
                            store_split(g_qhi, g_qlo, off, ox, oy);
                        } else {
                            size_t off = (((size_t)(bb * NKV + h)) * SEQ + s) * HD + d0;
                            store_split(g_khi, g_klo, off, ox, oy);
                        }
                    }
                }
            }
    }
}

// ==========================================================================
// Tensor-core flash attention, bf16-split operands, fp32 accum (round-4).
// ==========================================================================
#define AROW   272
#define QTB    (128 * AROW)
#define KVM    (64 * AROW)
#define KVSTG  (4 * KVM)
#define ATT_SMEM (2 * QTB + 2 * KVSTG)  // 208896

__global__ __launch_bounds__(256, 1)
void attn_kernel(const int* __restrict__ pos_ids)
{
    extern __shared__ char smem[];
    const uint32_t sb = cvta_smem(smem);
    const int tid = threadIdx.x;
    const int lane = tid & 31, wq = tid >> 5;
    const int qt = blockIdx.x, bh = blockIdx.y;
    const int b = bh >> 4, h = bh & 15, kvh = h >> 2;
    const int q0 = qt * 128;

    const size_t qbase = (((size_t)(b * NH + h)) * SEQ + q0) * HD;
    const size_t kvbase = ((size_t)(b * NKV + kvh)) * SEQ * HD;

#pragma unroll
    for (int it = 0; it < 16; it++) {
        int mat = it >> 3;
        int rem = (it & 7) * 256 + tid;
        int row = rem >> 4, ch = rem & 15;
        const __nv_bfloat16* src = (mat ? g_qlo : g_qhi) + qbase
                                   + (size_t)row * HD + ch * 8;
        cp16(sb + mat * QTB + row * AROW + ch * 16, src);
    }
    cp_commit();

    const int nkt = 2 * qt + 2;

    auto issue_kv = [&](int kt) {
        const uint32_t st = sb + 2 * QTB + (kt & 1) * KVSTG;
        const int k0 = kt * 64;
#pragma unroll
        for (int it = 0; it < 16; it++) {
            int mat = it >> 2;
            int rem = (it & 3) * 256 + tid;
            int row = rem >> 4, ch = rem & 15;
            const __nv_bfloat16* base =
                (mat == 0) ? g_khi : (mat == 1) ? g_klo
                : (mat == 2) ? g_vhi : g_vlo;
            cp16(st + mat * KVM + row * AROW + ch * 16,
                 base + kvbase + (size_t)(k0 + row) * HD + ch * 8);
        }
        cp_commit();
    };

    issue_kv(0);

    float m_lo = -1e30f, m_hi = -1e30f, l_lo = 0.f, l_hi = 0.f;
    float o_acc[16][4];
#pragma unroll
    for (int nt = 0; nt < 16; nt++)
#pragma unroll
        for (int j = 0; j < 4; j++) o_acc[nt][j] = 0.f;

    const int r_lo = lane >> 2;
    const int pq_lo = pos_ids[q0 + 16 * wq + r_lo];
    const int pq_hi = pos_ids[q0 + 16 * wq + r_lo + 8];

    const uint32_t q_a = sb + (16 * wq + (lane & 15)) * AROW + (lane >> 4) * 16;
    const uint32_t k_row = (lane & 7) + ((lane >> 4) << 3);
    const uint32_t k_cb  = ((lane >> 3) & 1) * 16;
    const uint32_t v_row = (lane & 7) + (((lane >> 3) & 1) << 3);
    const uint32_t v_cb  = (lane >> 4) * 16;

    for (int kt = 0; kt < nkt; kt++) {
        if (kt + 1 < nkt) { issue_kv(kt + 1); cp_wait<1>(); }
        else cp_wait<0>();
        __syncthreads();
        const uint32_t st = sb + 2 * QTB + (kt & 1) * KVSTG;
        const int k0 = kt * 64;

        float s_acc[8][4];
#pragma unroll
        for (int nt = 0; nt < 8; nt++)
#pragma unroll
            for (int j = 0; j < 4; j++) s_acc[nt][j] = 0.f;

#pragma unroll
        for (int kc = 0; kc < 8; kc++) {
            uint32_t ah[4], al[4];
            ldsm4(ah[0], ah[1], ah[2], ah[3], q_a + kc * 32);
            ldsm4(al[0], al[1], al[2], al[3], q_a + QTB + kc * 32);
#pragma unroll
            for (int kp = 0; kp < 4; kp++) {
                uint32_t kh[4], kl[4];
                uint32_t ka = st + (16 * kp + k_row) * AROW + kc * 32 + k_cb;
                ldsm4(kh[0], kh[1], kh[2], kh[3], ka);
                ldsm4(kl[0], kl[1], kl[2], kl[3], ka + KVM);
                mma16816(s_acc[2 * kp],     ah, &kh[0]);
                mma16816(s_acc[2 * kp],     ah, &kl[0]);
                mma16816(s_acc[2 * kp],     al, &kh[0]);
                mma16816(s_acc[2 * kp + 1], ah, &kh[2]);
                mma16816(s_acc[2 * kp + 1], ah, &kl[2]);
                mma16816(s_acc[2 * kp + 1], al, &kh[2]);
            }
        }

        if (k0 + 63 > pq_lo) {
#pragma unroll
            for (int nt = 0; nt < 8; nt++) {
                int c = k0 + 8 * nt + 2 * (lane & 3);
                if (c     > pq_lo) s_acc[nt][0] = -1e30f;
                if (c + 1 > pq_lo) s_acc[nt][1] = -1e30f;
                if (c     > pq_hi) s_acc[nt][2] = -1e30f;
                if (c + 1 > pq_hi) s_acc[nt][3] = -1e30f;
            }
        }

        float rm_lo = -1e30f, rm_hi = -1e30f;
#pragma unroll
        for (int nt = 0; nt < 8; nt++) {
            rm_lo = fmaxf(rm_lo, fmaxf(s_acc[nt][0], s_acc[nt][1]));
            rm_hi = fmaxf(rm_hi, fmaxf(s_acc[nt][2], s_acc[nt][3]));
        }
#pragma unroll
        for (int o = 1; o < 4; o <<= 1) {
            rm_lo = fmaxf(rm_lo, __shfl_xor_sync(0xffffffffu, rm_lo, o));
            rm_hi = fmaxf(rm_hi, __shfl_xor_sync(0xffffffffu, rm_hi, o));
        }
        float nm_lo = fmaxf(m_lo, rm_lo), nm_hi = fmaxf(m_hi, rm_hi);
        float corr_lo = __expf(m_lo - nm_lo), corr_hi = __expf(m_hi - nm_hi);
        m_lo = nm_lo; m_hi = nm_hi;
        float rs_lo = 0.f, rs_hi = 0.f;
#pragma unroll
        for (int nt = 0; nt < 8; nt++) {
            s_acc[nt][0] = __expf(s_acc[nt][0] - nm_lo);
            s_acc[nt][1] = __expf(s_acc[nt][1] - nm_lo);
            s_acc[nt][2] = __expf(s_acc[nt][2] - nm_hi);
            s_acc[nt][3] = __expf(s_acc[nt][3] - nm_hi);
            rs_lo += s_acc[nt][0] + s_acc[nt][1];
            rs_hi += s_acc[nt][2] + s_acc[nt][3];
        }
#pragma unroll
        for (int o = 1; o < 4; o <<= 1) {
            rs_lo += __shfl_xor_sync(0xffffffffu, rs_lo, o);
            rs_hi += __shfl_xor_sync(0xffffffffu, rs_hi, o);
        }
        l_lo = l_lo * corr_lo + rs_lo;
        l_hi = l_hi * corr_hi + rs_hi;
#pragma unroll
        for (int nt = 0; nt < 16; nt++) {
            o_acc[nt][0] *= corr_lo; o_acc[nt][1] *= corr_lo;
            o_acc[nt][2] *= corr_hi; o_acc[nt][3] *= corr_hi;
        }

#pragma unroll
        for (int kc2 = 0; kc2 < 4; kc2++) {
            uint32_t phi[4], plo[4];
            pack_split(s_acc[2 * kc2][0],     s_acc[2 * kc2][1],     phi[0], plo[0]);
            pack_split(s_acc[2 * kc2][2],     s_acc[2 * kc2][3],     phi[1], plo[1]);
            pack_split(s_acc[2 * kc2 + 1][0], s_acc[2 * kc2 + 1][1], phi[2], plo[2]);
            pack_split(s_acc[2 * kc2 + 1][2], s_acc[2 * kc2 + 1][3], phi[3], plo[3]);
#pragma unroll
            for (int nd = 0; nd < 8; nd++) {
                uint32_t vh[4], vl[4];
                uint32_t va = st + 2 * KVM + (16 * kc2 + v_row) * AROW
                              + nd * 32 + v_cb;
                ldsm4t(vh[0], vh[1], vh[2], vh[3], va);
                ldsm4t(vl[0], vl[1], vl[2], vl[3], va + KVM);
                mma16816(o_acc[2 * nd],     phi, &vh[0]);
                mma16816(o_acc[2 * nd],     phi, &vl[0]);
                mma16816(o_acc[2 * nd],     plo, &vh[0]);
                mma16816(o_acc[2 * nd + 1], phi, &vh[2]);
                mma16816(o_acc[2 * nd + 1], phi, &vl[2]);
                mma16816(o_acc[2 * nd + 1], plo, &vh[2]);
            }
        }
        __syncthreads();
    }

    float inv_lo = 1.0f / l_lo, inv_hi = 1.0f / l_hi;
    int row_lo = q0 + 16 * wq + r_lo;
#pragma unroll
    for (int nt = 0; nt < 16; nt++) {
        int col = h * HD + 8 * nt + 2 * (lane & 3);
        size_t off_lo = (size_t)(b * SEQ + row_lo) * NE + col;
        size_t off_hi = (size_t)(b * SEQ + row_lo + 8) * NE + col;
        store_split(g_yhi, g_ylo, off_lo, o_acc[nt][0] * inv_lo, o_acc[nt][1] * inv_lo);
        store_split(g_yhi, g_ylo, off_hi, o_acc[nt][2] * inv_hi, o_acc[nt][3] * inv_hi);
    }
}

// ==========================================================================
extern "C" void kernel_launch(void* const* d_in, const int* in_sizes, int n_in,
                              void* d_out, int out_size)
{
    const float* x   = (const float*)d_in[0];
    const float* Wq  = (const float*)d_in[1];
    const float* Wk  = (const float*)d_in[2];
    const float* Wv  = (const float*)d_in[3];
    const float* Wo  = (const float*)d_in[4];
    const int*   pos = (const int*)d_in[5];
    float* out = (float*)d_out;

    fill_rope_kernel<<<(SEQ * 64 + 255) / 256, 256>>>(pos);

    {
        int n4x = MTOT * NE / 4;
        split_x_kernel<<<(n4x + 255) / 256, 256>>>(x, n4x);
        int n4q = NH * HD * NE / 4;
        int n4k = NKV * HD * NE / 4;
        split_w_kernel<<<(n4q + 255) / 256, 256>>>(Wq, 0, n4q);
        split_w_kernel<<<(n4k + 255) / 256, 256>>>(Wk, (NH * HD) * NE / 4, n4k);
        split_w_kernel<<<(n4k + 255) / 256, 256>>>(Wv, (NH * HD + NKV * HD) * NE / 4, n4k);
        split_w_kernel<<<(n4q + 255) / 256, 256>>>(Wo, NQKV * NE / 4, n4q);
    }

    const int gsmem = NPIPE * STGB;   // 122880
    cudaFuncSetAttribute(gemm_kernel<0>,
                         cudaFuncAttributeMaxDynamicSharedMemorySize, gsmem);
    cudaFuncSetAttribute(gemm_kernel<1>,
                         cudaFuncAttributeMaxDynamicSharedMemorySize, gsmem);

    // QKV projection
    gemm_kernel<0><<<dim3(24, 32), 256, gsmem>>>(0, nullptr);

    // attention (tensor-core)
    cudaFuncSetAttribute(attn_kernel,
                         cudaFuncAttributeMaxDynamicSharedMemorySize, ATT_SMEM);
    attn_kernel<<<dim3(SEQ / 128, BATCH * NH), 256, ATT_SMEM>>>(pos);

    // output projection
    gemm_kernel<1><<<dim3(16, 32), 256, gsmem>>>(NQKV, out);
}

// round 6
// speedup vs baseline: 5.9015x; 2.1657x over previous
#include <cuda_runtime.h>
#include <cuda_fp16.h>
#include <cstdint>

#define NE    2048
#define NH    16
#define NKV   4
#define HD    128
#define SEQ   2048
#define BATCH 2
#define MTOT  (BATCH * SEQ)                 // 4096
#define NQKV  (NH * HD + 2 * NKV * HD)      // 3072

#define ROPE_L2 0.10381025296522976f
#define SC 0.08838834764831845f             // 1/sqrt(128)

// -------------------- device scratch (all single fp16) --------------------
__device__ float2 g_rope[SEQ * 64];

__device__ __half g_xh[(size_t)MTOT * NE];
__device__ __half g_wh[(size_t)(NQKV + NE) * NE];   // Wq|Wk|Wv|Wo rows
__device__ __half g_yh[(size_t)MTOT * NE];

__device__ __half g_qh[(size_t)BATCH * NH * SEQ * HD];
__device__ __half g_kh[(size_t)BATCH * NKV * SEQ * HD];
__device__ __half g_vh[(size_t)BATCH * NKV * SEQ * HD];

// -------------------- PTX helpers (plain-target only) --------------------
__device__ __forceinline__ uint32_t cvta_smem(const void* p) {
    uint32_t a;
    asm("{ .reg .u64 t; cvta.to.shared.u64 t, %1; cvt.u32.u64 %0, t; }"
        : "=r"(a) : "l"(p));
    return a;
}
__device__ __forceinline__ void cp16(uint32_t dst, const void* src) {
    asm volatile("cp.async.cg.shared.global [%0], [%1], 16;" :: "r"(dst), "l"(src));
}
__device__ __forceinline__ void cp_commit() {
    asm volatile("cp.async.commit_group;" ::: "memory");
}
template <int N>
__device__ __forceinline__ void cp_wait() {
    asm volatile("cp.async.wait_group %0;" :: "n"(N) : "memory");
}
__device__ __forceinline__ void ldsm4(uint32_t& r0, uint32_t& r1,
                                      uint32_t& r2, uint32_t& r3, uint32_t a) {
    asm volatile("ldmatrix.sync.aligned.m8n8.x4.shared.b16 {%0,%1,%2,%3}, [%4];"
                 : "=r"(r0), "=r"(r1), "=r"(r2), "=r"(r3) : "r"(a));
}
__device__ __forceinline__ void ldsm4t(uint32_t& r0, uint32_t& r1,
                                       uint32_t& r2, uint32_t& r3, uint32_t a) {
    asm volatile("ldmatrix.sync.aligned.m8n8.x4.trans.shared.b16 {%0,%1,%2,%3}, [%4];"
                 : "=r"(r0), "=r"(r1), "=r"(r2), "=r"(r3) : "r"(a));
}
__device__ __forceinline__ void mma16816(float* c, const uint32_t* a,
                                         const uint32_t* b) {
    asm volatile(
        "mma.sync.aligned.m16n8k16.row.col.f32.f16.f16.f32 "
        "{%0,%1,%2,%3}, {%4,%5,%6,%7}, {%8,%9}, {%0,%1,%2,%3};"
        : "+f"(c[0]), "+f"(c[1]), "+f"(c[2]), "+f"(c[3])
        : "r"(a[0]), "r"(a[1]), "r"(a[2]), "r"(a[3]), "r"(b[0]), "r"(b[1]));
}

__device__ __forceinline__ uint32_t pack_h2(float a, float b) {
    __half2 h = __floats2half2_rn(a, b);
    return *(uint32_t*)&h;
}

// -------------------- conversion kernels --------------------
__global__ void conv_x_kernel(const float* __restrict__ src, int n4) {
    int i = blockIdx.x * 256 + threadIdx.x;
    if (i >= n4) return;
    float4 v = ((const float4*)src)[i];
    ((uint2*)g_xh)[i] = make_uint2(pack_h2(v.x, v.y), pack_h2(v.z, v.w));
}
__global__ void conv_w_kernel(const float* __restrict__ src, int base4, int n4) {
    int i = blockIdx.x * 256 + threadIdx.x;
    if (i >= n4) return;
    float4 v = ((const float4*)src)[i];
    ((uint2*)g_wh)[base4 + i] = make_uint2(pack_h2(v.x, v.y), pack_h2(v.z, v.w));
}
__global__ void fill_rope_kernel(const int* __restrict__ pos_ids) {
    int idx = blockIdx.x * 256 + threadIdx.x;
    if (idx >= SEQ * 64) return;
    int s = idx >> 6, p = idx & 63;
    float pos = (float)pos_ids[s];
    float f = pos * exp2f(-(float)(2 * p) * ROPE_L2);
    float sn, cs;
    sincosf(f, &sn, &cs);
    g_rope[idx] = make_float2(cs, sn);
}

// ==========================================================================
// single-fp16 tensor-core GEMM:  C[m,n] = sum_k A[m,k] * W[n,k]
// CTA tile 128x128, 256 threads (8 warps, 2x4), warp tile 64x32.
// K-chunk 32, 4-stage cp.async pipeline, rows padded to 80B.
// MODE 0: A = g_xh, RoPE + scatter fp16 to q/k/v (Q pre-scaled by SC)
// MODE 1: A = g_yh, fp32 store to outp
// ==========================================================================
#define KCH     32
#define NSTG    (NE / KCH)       // 64
#define ROWB    80
#define MATB    (128 * ROWB)     // 10240
#define STGB    (2 * MATB)       // 20480 per stage: A | B
#define NPIPE   4

template <int MODE>
__global__ __launch_bounds__(256, 1)
void gemm_kernel(int browbase, float* __restrict__ outp)
{
    extern __shared__ char smem[];
    const uint32_t sb = cvta_smem(smem);
    const int tid  = threadIdx.x;
    const int wid  = tid >> 5, lane = tid & 31;
    const int wm   = (wid >> 2) * 64;
    const int wn   = (wid & 3) * 32;
    const int bn   = blockIdx.x * 128;
    const int bm   = blockIdx.y * 128;

    const __half* A = (MODE == 0) ? g_xh : g_yh;

    float acc[4][4][4];
#pragma unroll
    for (int f = 0; f < 4; f++)
#pragma unroll
        for (int n = 0; n < 4; n++)
#pragma unroll
            for (int q = 0; q < 4; q++) acc[f][n][q] = 0.f;

    const int r0i = tid >> 2;
    const int c0i = tid & 3;
    const uint32_t ldst0 = (uint32_t)(r0i * ROWB + c0i * 16);
    const uint32_t ldst1 = (uint32_t)((r0i + 64) * ROWB + c0i * 16);
    const size_t gA0 = (size_t)(bm + r0i) * NE + c0i * 8;
    const size_t gA1 = (size_t)(bm + r0i + 64) * NE + c0i * 8;
    const size_t gB0 = (size_t)(browbase + bn + r0i) * NE + c0i * 8;
    const size_t gB1 = (size_t)(browbase + bn + r0i + 64) * NE + c0i * 8;

    const uint32_t aoff = (uint32_t)((wm + (lane & 15)) * ROWB + (lane >> 4) * 16);
    const uint32_t boff = (uint32_t)((wn + (lane & 7) + ((lane >> 4) << 3)) * ROWB
                                     + ((lane >> 3) & 1) * 16);

    auto issue = [&](int s) {
        const uint32_t st = sb + (s % NPIPE) * STGB;
        const size_t ko = (size_t)s * KCH;
        cp16(st + ldst0,        A + gA0 + ko);
        cp16(st + ldst1,        A + gA1 + ko);
        cp16(st + MATB + ldst0, g_wh + gB0 + ko);
        cp16(st + MATB + ldst1, g_wh + gB1 + ko);
        cp_commit();
    };

    issue(0);
    issue(1);
    issue(2);

    for (int s = 0; s < NSTG; s++) {
        if (s + 3 < NSTG) { issue(s + 3); cp_wait<3>(); }
        else if (s + 2 < NSTG) cp_wait<2>();
        else if (s + 1 < NSTG) cp_wait<1>();
        else cp_wait<0>();
        __syncthreads();

        const uint32_t st = sb + (s % NPIPE) * STGB;
#pragma unroll
        for (int t = 0; t < 2; t++) {
            uint32_t bh[8];
#pragma unroll
            for (int g = 0; g < 2; g++)
                ldsm4(bh[g * 4 + 0], bh[g * 4 + 1], bh[g * 4 + 2], bh[g * 4 + 3],
                      st + MATB + boff + g * 16 * ROWB + t * 32);
#pragma unroll
            for (int f = 0; f < 4; f++) {
                uint32_t ah[4];
                ldsm4(ah[0], ah[1], ah[2], ah[3],
                      st + aoff + f * 16 * ROWB + t * 32);
#pragma unroll
                for (int n = 0; n < 4; n++)
                    mma16816(acc[f][n], ah, &bh[n * 2]);
            }
        }
        __syncthreads();
    }

    const int r0 = lane >> 2;
    const int c0 = (lane & 3) * 2;

    if (MODE == 1) {
#pragma unroll
        for (int f = 0; f < 4; f++)
#pragma unroll
            for (int n = 0; n < 4; n++) {
                int m = bm + wm + f * 16 + r0;
                int c = bn + wn + n * 8 + c0;
                *(float2*)&outp[(size_t)m * NE + c] =
                    make_float2(acc[f][n][0], acc[f][n][1]);
                *(float2*)&outp[(size_t)(m + 8) * NE + c] =
                    make_float2(acc[f][n][2], acc[f][n][3]);
            }
    } else {
        const int region = (bn < NH * HD) ? 0 : ((bn < NH * HD + NKV * HD) ? 1 : 2);
#pragma unroll
        for (int f = 0; f < 4; f++)
#pragma unroll
            for (int n = 0; n < 4; n++) {
                int nglob = bn + wn + n * 8 + c0;
#pragma unroll
                for (int half = 0; half < 2; half++) {
                    int m = bm + wm + f * 16 + r0 + half * 8;
                    int bb = m >> 11, s = m & (SEQ - 1);
                    float v0 = acc[f][n][half * 2 + 0];
                    float v1 = acc[f][n][half * 2 + 1];
                    if (region == 2) {
                        int nl = nglob - NH * HD - NKV * HD;
                        int h = nl >> 7, d0 = nl & 127;
                        size_t off = (((size_t)(bb * NKV + h)) * SEQ + s) * HD + d0;
                        *(uint32_t*)&g_vh[off] = pack_h2(v0, v1);
                    } else {
                        int nl = (region == 0) ? nglob : (nglob - NH * HD);
                        int h = nl >> 7, d0 = nl & 127;
                        float2 cs = g_rope[s * 64 + (d0 >> 1)];
                        float ox = v0 * cs.x - v1 * cs.y;
                        float oy = v1 * cs.x + v0 * cs.y;
                        if (region == 0) {
                            ox *= SC; oy *= SC;
                            size_t off = (((size_t)(bb * NH + h)) * SEQ + s) * HD + d0;
                            *(uint32_t*)&g_qh[off] = pack_h2(ox, oy);
                        } else {
                            size_t off = (((size_t)(bb * NKV + h)) * SEQ + s) * HD + d0;
                            *(uint32_t*)&g_kh[off] = pack_h2(ox, oy);
                        }
                    }
                }
            }
    }
}

// ==========================================================================
// Tensor-core flash attention, single-fp16 operands, fp32 accum.
// CTA: 128 q-rows x (b,h). 8 warps. K/V tiles of 64 keys, double-buffered.
// ==========================================================================
#define AROW   272
#define QTB    (128 * AROW)             // 34816
#define KVM    (64 * AROW)              // 17408
#define KVSTG  (2 * KVM)                // 34816 per stage: K | V
#define ATT_SMEM (QTB + 2 * KVSTG)      // 104448

__global__ __launch_bounds__(256, 1)
void attn_kernel(const int* __restrict__ pos_ids)
{
    extern __shared__ char smem[];
    const uint32_t sb = cvta_smem(smem);
    const int tid = threadIdx.x;
    const int lane = tid & 31, wq = tid >> 5;
    const int qt = gridDim.x - 1 - blockIdx.x;   // heavy tiles first
    const int bh = blockIdx.y;
    const int b = bh >> 4, h = bh & 15, kvh = h >> 2;
    const int q0 = qt * 128;

    const size_t qbase = (((size_t)(b * NH + h)) * SEQ + q0) * HD;
    const size_t kvbase = ((size_t)(b * NKV + kvh)) * SEQ * HD;

    // ---- load Q ----
#pragma unroll
    for (int it = 0; it < 8; it++) {
        int rem = it * 256 + tid;          // 0..2047
        int row = rem >> 4, ch = rem & 15;
        cp16(sb + row * AROW + ch * 16,
             g_qh + qbase + (size_t)row * HD + ch * 8);
    }
    cp_commit();

    const int nkt = 2 * qt + 2;

    auto issue_kv = [&](int kt) {
        const uint32_t st = sb + QTB + (kt & 1) * KVSTG;
        const int k0 = kt * 64;
#pragma unroll
        for (int it = 0; it < 8; it++) {
            int mat = it >> 2;                 // 0 = K, 1 = V
            int rem = (it & 3) * 256 + tid;    // 0..1023
            int row = rem >> 4, ch = rem & 15;
            const __half* base = mat ? g_vh : g_kh;
            cp16(st + mat * KVM + row * AROW + ch * 16,
                 base + kvbase + (size_t)(k0 + row) * HD + ch * 8);
        }
        cp_commit();
    };

    issue_kv(0);

    float m_lo = -1e30f, m_hi = -1e30f, l_lo = 0.f, l_hi = 0.f;
    float o_acc[16][4];
#pragma unroll
    for (int nt = 0; nt < 16; nt++)
#pragma unroll
        for (int j = 0; j < 4; j++) o_acc[nt][j] = 0.f;

    const int r_lo = lane >> 2;
    const int pq_lo = pos_ids[q0 + 16 * wq + r_lo];
    const int pq_hi = pos_ids[q0 + 16 * wq + r_lo + 8];

    const uint32_t q_a = sb + (16 * wq + (lane & 15)) * AROW + (lane >> 4) * 16;
    const uint32_t k_row = (lane & 7) + ((lane >> 4) << 3);
    const uint32_t k_cb  = ((lane >> 3) & 1) * 16;
    const uint32_t v_row = (lane & 7) + (((lane >> 3) & 1) << 3);
    const uint32_t v_cb  = (lane >> 4) * 16;

    for (int kt = 0; kt < nkt; kt++) {
        if (kt + 1 < nkt) { issue_kv(kt + 1); cp_wait<1>(); }
        else cp_wait<0>();
        __syncthreads();
        const uint32_t st = sb + QTB + (kt & 1) * KVSTG;
        const int k0 = kt * 64;

        // ---- S = Q K^T ----
        float s_acc[8][4];
#pragma unroll
        for (int nt = 0; nt < 8; nt++)
#pragma unroll
            for (int j = 0; j < 4; j++) s_acc[nt][j] = 0.f;

#pragma unroll
        for (int kc = 0; kc < 8; kc++) {
            uint32_t ah[4];
            ldsm4(ah[0], ah[1], ah[2], ah[3], q_a + kc * 32);
#pragma unroll
            for (int kp = 0; kp < 4; kp++) {
                uint32_t kh[4];
                ldsm4(kh[0], kh[1], kh[2], kh[3],
                      st + (16 * kp + k_row) * AROW + kc * 32 + k_cb);
                mma16816(s_acc[2 * kp],     ah, &kh[0]);
                mma16816(s_acc[2 * kp + 1], ah, &kh[2]);
            }
        }

        // ---- causal mask ----
        if (k0 + 63 > pq_lo) {
#pragma unroll
            for (int nt = 0; nt < 8; nt++) {
                int c = k0 + 8 * nt + 2 * (lane & 3);
                if (c     > pq_lo) s_acc[nt][0] = -1e30f;
                if (c + 1 > pq_lo) s_acc[nt][1] = -1e30f;
                if (c     > pq_hi) s_acc[nt][2] = -1e30f;
                if (c + 1 > pq_hi) s_acc[nt][3] = -1e30f;
            }
        }

        // ---- online softmax ----
        float rm_lo = -1e30f, rm_hi = -1e30f;
#pragma unroll
        for (int nt = 0; nt < 8; nt++) {
            rm_lo = fmaxf(rm_lo, fmaxf(s_acc[nt][0], s_acc[nt][1]));
            rm_hi = fmaxf(rm_hi, fmaxf(s_acc[nt][2], s_acc[nt][3]));
        }
#pragma unroll
        for (int o = 1; o < 4; o <<= 1) {
            rm_lo = fmaxf(rm_lo, __shfl_xor_sync(0xffffffffu, rm_lo, o));
            rm_hi = fmaxf(rm_hi, __shfl_xor_sync(0xffffffffu, rm_hi, o));
        }
        float nm_lo = fmaxf(m_lo, rm_lo), nm_hi = fmaxf(m_hi, rm_hi);
        float corr_lo = __expf(m_lo - nm_lo), corr_hi = __expf(m_hi - nm_hi);
        m_lo = nm_lo; m_hi = nm_hi;
        float rs_lo = 0.f, rs_hi = 0.f;
#pragma unroll
        for (int nt = 0; nt < 8; nt++) {
            s_acc[nt][0] = __expf(s_acc[nt][0] - nm_lo);
            s_acc[nt][1] = __expf(s_acc[nt][1] - nm_lo);
            s_acc[nt][2] = __expf(s_acc[nt][2] - nm_hi);
            s_acc[nt][3] = __expf(s_acc[nt][3] - nm_hi);
            rs_lo += s_acc[nt][0] + s_acc[nt][1];
            rs_hi += s_acc[nt][2] + s_acc[nt][3];
        }
#pragma unroll
        for (int o = 1; o < 4; o <<= 1) {
            rs_lo += __shfl_xor_sync(0xffffffffu, rs_lo, o);
            rs_hi += __shfl_xor_sync(0xffffffffu, rs_hi, o);
        }
        l_lo = l_lo * corr_lo + rs_lo;
        l_hi = l_hi * corr_hi + rs_hi;
#pragma unroll
        for (int nt = 0; nt < 16; nt++) {
            o_acc[nt][0] *= corr_lo; o_acc[nt][1] *= corr_lo;
            o_acc[nt][2] *= corr_hi; o_acc[nt][3] *= corr_hi;
        }

        // ---- O += P V ----
#pragma unroll
        for (int kc2 = 0; kc2 < 4; kc2++) {
            uint32_t p[4];
            p[0] = pack_h2(s_acc[2 * kc2][0],     s_acc[2 * kc2][1]);
            p[1] = pack_h2(s_acc[2 * kc2][2],     s_acc[2 * kc2][3]);
            p[2] = pack_h2(s_acc[2 * kc2 + 1][0], s_acc[2 * kc2 + 1][1]);
            p[3] = pack_h2(s_acc[2 * kc2 + 1][2], s_acc[2 * kc2 + 1][3]);
#pragma unroll
            for (int nd = 0; nd < 8; nd++) {
                uint32_t vh[4];
                ldsm4t(vh[0], vh[1], vh[2], vh[3],
                       st + KVM + (16 * kc2 + v_row) * AROW + nd * 32 + v_cb);
                mma16816(o_acc[2 * nd],     p, &vh[0]);
                mma16816(o_acc[2 * nd + 1], p, &vh[2]);
            }
        }
        __syncthreads();
    }

    // ---- epilogue: normalize + store y as fp16 ----
    float inv_lo = 1.0f / l_lo, inv_hi = 1.0f / l_hi;
    int row_lo = q0 + 16 * wq + r_lo;
#pragma unroll
    for (int nt = 0; nt < 16; nt++) {
        int col = h * HD + 8 * nt + 2 * (lane & 3);
        size_t off_lo = (size_t)(b * SEQ + row_lo) * NE + col;
        size_t off_hi = (size_t)(b * SEQ + row_lo + 8) * NE + col;
        *(uint32_t*)&g_yh[off_lo] = pack_h2(o_acc[nt][0] * inv_lo, o_acc[nt][1] * inv_lo);
        *(uint32_t*)&g_yh[off_hi] = pack_h2(o_acc[nt][2] * inv_hi, o_acc[nt][3] * inv_hi);
    }
}

// ==========================================================================
extern "C" void kernel_launch(void* const* d_in, const int* in_sizes, int n_in,
                              void* d_out, int out_size)
{
    const float* x   = (const float*)d_in[0];
    const float* Wq  = (const float*)d_in[1];
    const float* Wk  = (const float*)d_in[2];
    const float* Wv  = (const float*)d_in[3];
    const float* Wo  = (const float*)d_in[4];
    const int*   pos = (const int*)d_in[5];
    float* out = (float*)d_out;

    fill_rope_kernel<<<(SEQ * 64 + 255) / 256, 256>>>(pos);

    {
        int n4x = MTOT * NE / 4;
        conv_x_kernel<<<(n4x + 255) / 256, 256>>>(x, n4x);
        int n4q = NH * HD * NE / 4;
        int n4k = NKV * HD * NE / 4;
        conv_w_kernel<<<(n4q + 255) / 256, 256>>>(Wq, 0, n4q);
        conv_w_kernel<<<(n4k + 255) / 256, 256>>>(Wk, (NH * HD) * NE / 4, n4k);
        conv_w_kernel<<<(n4k + 255) / 256, 256>>>(Wv, (NH * HD + NKV * HD) * NE / 4, n4k);
        conv_w_kernel<<<(n4q + 255) / 256, 256>>>(Wo, NQKV * NE / 4, n4q);
    }

    const int gsmem = NPIPE * STGB;   // 81920
    cudaFuncSetAttribute(gemm_kernel<0>,
                         cudaFuncAttributeMaxDynamicSharedMemorySize, gsmem);
    cudaFuncSetAttribute(gemm_kernel<1>,
                         cudaFuncAttributeMaxDynamicSharedMemorySize, gsmem);

    // QKV projection
    gemm_kernel<0><<<dim3(24, 32), 256, gsmem>>>(0, nullptr);

    // attention (tensor-core, single fp16)
    cudaFuncSetAttribute(attn_kernel,
                         cudaFuncAttributeMaxDynamicSharedMemorySize, ATT_SMEM);
    attn_kernel<<<dim3(SEQ / 128, BATCH * NH), 256, ATT_SMEM>>>(pos);

    // output projection
    gemm_kernel<1><<<dim3(16, 32), 256, gsmem>>>(NQKV, out);
}

// round 7
// speedup vs baseline: 6.8492x; 1.1606x over previous
#include <cuda_runtime.h>
#include <cuda_fp16.h>
#include <cstdint>

#define NE    2048
#define NH    16
#define NKV   4
#define HD    128
#define SEQ   2048
#define BATCH 2
#define MTOT  (BATCH * SEQ)                 // 4096
#define NQKV  (NH * HD + 2 * NKV * HD)      // 3072

#define ROPE_L2 0.10381025296522976f
#define SC 0.08838834764831845f             // 1/sqrt(128)

// -------------------- device scratch (all single fp16) --------------------
__device__ float2 g_rope[SEQ * 64];

__device__ __half g_xh[(size_t)MTOT * NE];
__device__ __half g_wh[(size_t)(NQKV + NE) * NE];   // Wq|Wk|Wv|Wo rows
__device__ __half g_yh[(size_t)MTOT * NE];

__device__ __half g_qh[(size_t)BATCH * NH * SEQ * HD];
__device__ __half g_kh[(size_t)BATCH * NKV * SEQ * HD];
__device__ __half g_vh[(size_t)BATCH * NKV * SEQ * HD];

// -------------------- PTX helpers (plain-target only) --------------------
__device__ __forceinline__ uint32_t cvta_smem(const void* p) {
    uint32_t a;
    asm("{ .reg .u64 t; cvta.to.shared.u64 t, %1; cvt.u32.u64 %0, t; }"
        : "=r"(a) : "l"(p));
    return a;
}
__device__ __forceinline__ void cp16(uint32_t dst, const void* src) {
    asm volatile("cp.async.cg.shared.global [%0], [%1], 16;" :: "r"(dst), "l"(src));
}
__device__ __forceinline__ void cp_commit() {
    asm volatile("cp.async.commit_group;" ::: "memory");
}
template <int N>
__device__ __forceinline__ void cp_wait() {
    asm volatile("cp.async.wait_group %0;" :: "n"(N) : "memory");
}
__device__ __forceinline__ void ldsm4(uint32_t& r0, uint32_t& r1,
                                      uint32_t& r2, uint32_t& r3, uint32_t a) {
    asm volatile("ldmatrix.sync.aligned.m8n8.x4.shared.b16 {%0,%1,%2,%3}, [%4];"
                 : "=r"(r0), "=r"(r1), "=r"(r2), "=r"(r3) : "r"(a));
}
__device__ __forceinline__ void ldsm4t(uint32_t& r0, uint32_t& r1,
                                       uint32_t& r2, uint32_t& r3, uint32_t a) {
    asm volatile("ldmatrix.sync.aligned.m8n8.x4.trans.shared.b16 {%0,%1,%2,%3}, [%4];"
                 : "=r"(r0), "=r"(r1), "=r"(r2), "=r"(r3) : "r"(a));
}
__device__ __forceinline__ void mma16816(float* c, const uint32_t* a,
                                         const uint32_t* b) {
    asm volatile(
        "mma.sync.aligned.m16n8k16.row.col.f32.f16.f16.f32 "
        "{%0,%1,%2,%3}, {%4,%5,%6,%7}, {%8,%9}, {%0,%1,%2,%3};"
        : "+f"(c[0]), "+f"(c[1]), "+f"(c[2]), "+f"(c[3])
        : "r"(a[0]), "r"(a[1]), "r"(a[2]), "r"(a[3]), "r"(b[0]), "r"(b[1]));
}

__device__ __forceinline__ uint32_t pack_h2(float a, float b) {
    __half2 h = __floats2half2_rn(a, b);
    return *(uint32_t*)&h;
}

// -------------------- merged conversion kernel --------------------
#define N4X (MTOT * NE / 4)                 // 2097152
#define N4Q (NH * HD * NE / 4)              // 1048576
#define N4K (NKV * HD * NE / 4)             // 262144
#define N4ALL (N4X + 2 * N4Q + 2 * N4K)     // 4718592

__global__ void conv_all_kernel(const float* __restrict__ x,
                                const float* __restrict__ Wq,
                                const float* __restrict__ Wk,
                                const float* __restrict__ Wv,
                                const float* __restrict__ Wo)
{
    int i = blockIdx.x * 256 + threadIdx.x;
    if (i >= N4ALL) return;
    const float4* src;
    uint2* dst;
    if (i < N4X) {
        src = (const float4*)x + i;
        dst = (uint2*)g_xh + i;
    } else {
        int j = i - N4X;
        if (j < N4Q) {
            src = (const float4*)Wq + j;
            dst = (uint2*)g_wh + j;
        } else if (j < N4Q + N4K) {
            src = (const float4*)Wk + (j - N4Q);
            dst = (uint2*)g_wh + j;
        } else if (j < N4Q + 2 * N4K) {
            src = (const float4*)Wv + (j - N4Q - N4K);
            dst = (uint2*)g_wh + j;
        } else {
            src = (const float4*)Wo + (j - N4Q - 2 * N4K);
            dst = (uint2*)g_wh + j;
        }
    }
    float4 v = *src;
    *dst = make_uint2(pack_h2(v.x, v.y), pack_h2(v.z, v.w));
}

__global__ void fill_rope_kernel(const int* __restrict__ pos_ids) {
    int idx = blockIdx.x * 256 + threadIdx.x;
    if (idx >= SEQ * 64) return;
    int s = idx >> 6, p = idx & 63;
    float pos = (float)pos_ids[s];
    float f = pos * exp2f(-(float)(2 * p) * ROPE_L2);
    float sn, cs;
    sincosf(f, &sn, &cs);
    g_rope[idx] = make_float2(cs, sn);
}

// ==========================================================================
// single-fp16 tensor-core GEMM:  C[m,n] = sum_k A[m,k] * W[n,k]
// CTA tile 128(M) x 256(N), 256 threads (8 warps, 2x4), warp tile 64x64.
// K-chunk 64, 3-stage cp.async pipeline, rows padded to 144B.
// MODE 0: A = g_xh, RoPE + scatter fp16 to q/k/v (Q pre-scaled by SC)
// MODE 1: A = g_yh, fp32 store to outp
// ==========================================================================
#define KCH     64
#define NSTG    (NE / KCH)       // 32
#define ROWB    144              // 128B data + 16B pad
#define MATA    (128 * ROWB)     // 18432 (A tile)
#define STGB    (MATA + 256 * ROWB)  // 55296 per stage: A | B
#define NPIPE   3

template <int MODE>
__global__ __launch_bounds__(256, 1)
void gemm_kernel(int browbase, float* __restrict__ outp)
{
    extern __shared__ char smem[];
    const uint32_t sb = cvta_smem(smem);
    const int tid  = threadIdx.x;
    const int wid  = tid >> 5, lane = tid & 31;
    const int wm   = (wid >> 2) * 64;        // warp m-offset (0 or 64)
    const int wn   = (wid & 3) * 64;         // warp n-offset (0,64,128,192)
    const int bn   = blockIdx.x * 256;
    const int bm   = blockIdx.y * 128;

    const __half* A = (MODE == 0) ? g_xh : g_yh;

    float acc[4][8][4];
#pragma unroll
    for (int f = 0; f < 4; f++)
#pragma unroll
        for (int n = 0; n < 8; n++)
#pragma unroll
            for (int q = 0; q < 4; q++) acc[f][n][q] = 0.f;

    // loads: A 128 rows x 8 chunks = 1024; B 256 rows x 8 chunks = 2048
    const int lrow = tid >> 3;               // 0..31
    const int lch  = tid & 7;                // chunk 0..7

    const uint32_t aoff = (uint32_t)((wm + (lane & 15)) * ROWB + (lane >> 4) * 16);
    const uint32_t boff = (uint32_t)(MATA
        + (wn + (lane & 7) + ((lane >> 4) << 3)) * ROWB
        + ((lane >> 3) & 1) * 16);

    auto issue = [&](int s) {
        const uint32_t st = sb + (s % NPIPE) * STGB;
        const size_t ko = (size_t)s * KCH + lch * 8;
#pragma unroll
        for (int it = 0; it < 4; it++) {
            int r = lrow + it * 32;
            cp16(st + r * ROWB + lch * 16, A + (size_t)(bm + r) * NE + ko);
        }
#pragma unroll
        for (int it = 0; it < 8; it++) {
            int r = lrow + it * 32;
            cp16(st + MATA + r * ROWB + lch * 16,
                 g_wh + (size_t)(browbase + bn + r) * NE + ko);
        }
        cp_commit();
    };

    issue(0);
    issue(1);

    for (int s = 0; s < NSTG; s++) {
        if (s + 2 < NSTG) { issue(s + 2); cp_wait<2>(); }
        else if (s + 1 < NSTG) cp_wait<1>();
        else cp_wait<0>();
        __syncthreads();

        const uint32_t st = sb + (s % NPIPE) * STGB;
#pragma unroll
        for (int t = 0; t < 4; t++) {
            uint32_t bh[16];
#pragma unroll
            for (int g = 0; g < 4; g++)
                ldsm4(bh[g * 4 + 0], bh[g * 4 + 1], bh[g * 4 + 2], bh[g * 4 + 3],
                      st + boff + g * 16 * ROWB + t * 32);
#pragma unroll
            for (int f = 0; f < 4; f++) {
                uint32_t ah[4];
                ldsm4(ah[0], ah[1], ah[2], ah[3],
                      st + aoff + f * 16 * ROWB + t * 32);
#pragma unroll
                for (int n = 0; n < 8; n++)
                    mma16816(acc[f][n], ah, &bh[n * 2]);
            }
        }
        __syncthreads();
    }

    const int r0 = lane >> 2;
    const int c0 = (lane & 3) * 2;

    if (MODE == 1) {
#pragma unroll
        for (int f = 0; f < 4; f++)
#pragma unroll
            for (int n = 0; n < 8; n++) {
                int m = bm + wm + f * 16 + r0;
                int c = bn + wn + n * 8 + c0;
                *(float2*)&outp[(size_t)m * NE + c] =
                    make_float2(acc[f][n][0], acc[f][n][1]);
                *(float2*)&outp[(size_t)(m + 8) * NE + c] =
                    make_float2(acc[f][n][2], acc[f][n][3]);
            }
    } else {
        // bn tiles of 256 are region-aligned: [0,2048)=Q, [2048,2560)=K,
        // [2560,3072)=V; 2048 and 2560 are multiples of 256.
        const int region = (bn < NH * HD) ? 0 : ((bn < NH * HD + NKV * HD) ? 1 : 2);
#pragma unroll
        for (int f = 0; f < 4; f++)
#pragma unroll
            for (int n = 0; n < 8; n++) {
                int nglob = bn + wn + n * 8 + c0;
#pragma unroll
                for (int half = 0; half < 2; half++) {
                    int m = bm + wm + f * 16 + r0 + half * 8;
                    int bb = m >> 11, s = m & (SEQ - 1);
                    float v0 = acc[f][n][half * 2 + 0];
                    float v1 = acc[f][n][half * 2 + 1];
                    if (region == 2) {
                        int nl = nglob - NH * HD - NKV * HD;
                        int h = nl >> 7, d0 = nl & 127;
                        size_t off = (((size_t)(bb * NKV + h)) * SEQ + s) * HD + d0;
                        *(uint32_t*)&g_vh[off] = pack_h2(v0, v1);
                    } else {
                        int nl = (region == 0) ? nglob : (nglob - NH * HD);
                        int h = nl >> 7, d0 = nl & 127;
                        float2 cs = g_rope[s * 64 + (d0 >> 1)];
                        float ox = v0 * cs.x - v1 * cs.y;
                        float oy = v1 * cs.x + v0 * cs.y;
                        if (region == 0) {
                            ox *= SC; oy *= SC;
                            size_t off = (((size_t)(bb * NH + h)) * SEQ + s) * HD + d0;
                            *(uint32_t*)&g_qh[off] = pack_h2(ox, oy);
                        } else {
                            size_t off = (((size_t)(bb * NKV + h)) * SEQ + s) * HD + d0;
                            *(uint32_t*)&g_kh[off] = pack_h2(ox, oy);
                        }
                    }
                }
            }
    }
}

// ==========================================================================
// Tensor-core flash attention, single-fp16 operands, fp32 accum.
// CTA: 128 q-rows x (b,h). 8 warps. K/V tiles of 64 keys, double-buffered.
// Occupancy 2 (128-reg cap, 104448B smem/CTA -> 204KB/SM).
// ==========================================================================
#define AROW   272
#define QTB    (128 * AROW)             // 34816
#define KVM    (64 * AROW)              // 17408
#define KVSTG  (2 * KVM)                // 34816 per stage: K | V
#define ATT_SMEM (QTB + 2 * KVSTG)      // 104448

__global__ void __launch_bounds__(256, 2)
attn_kernel(const int* __restrict__ pos_ids)
{
    extern __shared__ char smem[];
    const uint32_t sb = cvta_smem(smem);
    const int tid = threadIdx.x;
    const int lane = tid & 31, wq = tid >> 5;
    const int qt = gridDim.x - 1 - blockIdx.x;   // heavy tiles first
    const int bh = blockIdx.y;
    const int b = bh >> 4, h = bh & 15, kvh = h >> 2;
    const int q0 = qt * 128;

    const size_t qbase = (((size_t)(b * NH + h)) * SEQ + q0) * HD;
    const size_t kvbase = ((size_t)(b * NKV + kvh)) * SEQ * HD;

    // ---- load Q ----
#pragma unroll
    for (int it = 0; it < 8; it++) {
        int rem = it * 256 + tid;
        int row = rem >> 4, ch = rem & 15;
        cp16(sb + row * AROW + ch * 16,
             g_qh + qbase + (size_t)row * HD + ch * 8);
    }
    cp_commit();

    const int nkt = 2 * qt + 2;

    auto issue_kv = [&](int kt) {
        const uint32_t st = sb + QTB + (kt & 1) * KVSTG;
        const int k0 = kt * 64;
#pragma unroll
        for (int it = 0; it < 8; it++) {
            int mat = it >> 2;
            int rem = (it & 3) * 256 + tid;
            int row = rem >> 4, ch = rem & 15;
            const __half* base = mat ? g_vh : g_kh;
            cp16(st + mat * KVM + row * AROW + ch * 16,
                 base + kvbase + (size_t)(k0 + row) * HD + ch * 8);
        }
        cp_commit();
    };

    issue_kv(0);

    float m_lo = -1e30f, m_hi = -1e30f, l_lo = 0.f, l_hi = 0.f;
    float o_acc[16][4];
#pragma unroll
    for (int nt = 0; nt < 16; nt++)
#pragma unroll
        for (int j = 0; j < 4; j++) o_acc[nt][j] = 0.f;

    const int r_lo = lane >> 2;
    const int pq_lo = pos_ids[q0 + 16 * wq + r_lo];
    const int pq_hi = pos_ids[q0 + 16 * wq + r_lo + 8];

    const uint32_t q_a = sb + (16 * wq + (lane & 15)) * AROW + (lane >> 4) * 16;
    const uint32_t k_row = (lane & 7) + ((lane >> 4) << 3);
    const uint32_t k_cb  = ((lane >> 3) & 1) * 16;
    const uint32_t v_row = (lane & 7) + (((lane >> 3) & 1) << 3);
    const uint32_t v_cb  = (lane >> 4) * 16;

    for (int kt = 0; kt < nkt; kt++) {
        if (kt + 1 < nkt) { issue_kv(kt + 1); cp_wait<1>(); }
        else cp_wait<0>();
        __syncthreads();
        const uint32_t st = sb + QTB + (kt & 1) * KVSTG;
        const int k0 = kt * 64;

        // ---- S = Q K^T ----
        float s_acc[8][4];
#pragma unroll
        for (int nt = 0; nt < 8; nt++)
#pragma unroll
            for (int j = 0; j < 4; j++) s_acc[nt][j] = 0.f;

#pragma unroll
        for (int kc = 0; kc < 8; kc++) {
            uint32_t ah[4];
            ldsm4(ah[0], ah[1], ah[2], ah[3], q_a + kc * 32);
#pragma unroll
            for (int kp = 0; kp < 4; kp++) {
                uint32_t kh[4];
                ldsm4(kh[0], kh[1], kh[2], kh[3],
                      st + (16 * kp + k_row) * AROW + kc * 32 + k_cb);
                mma16816(s_acc[2 * kp],     ah, &kh[0]);
                mma16816(s_acc[2 * kp + 1], ah, &kh[2]);
            }
        }

        // ---- causal mask ----
        if (k0 + 63 > pq_lo) {
#pragma unroll
            for (int nt = 0; nt < 8; nt++) {
                int c = k0 + 8 * nt + 2 * (lane & 3);
                if (c     > pq_lo) s_acc[nt][0] = -1e30f;
                if (c + 1 > pq_lo) s_acc[nt][1] = -1e30f;
                if (c     > pq_hi) s_acc[nt][2] = -1e30f;
                if (c + 1 > pq_hi) s_acc[nt][3] = -1e30f;
            }
        }

        // ---- online softmax ----
        float rm_lo = -1e30f, rm_hi = -1e30f;
#pragma unroll
        for (int nt = 0; nt < 8; nt++) {
            rm_lo = fmaxf(rm_lo, fmaxf(s_acc[nt][0], s_acc[nt][1]));
            rm_hi = fmaxf(rm_hi, fmaxf(s_acc[nt][2], s_acc[nt][3]));
        }
#pragma unroll
        for (int o = 1; o < 4; o <<= 1) {
            rm_lo = fmaxf(rm_lo, __shfl_xor_sync(0xffffffffu, rm_lo, o));
            rm_hi = fmaxf(rm_hi, __shfl_xor_sync(0xffffffffu, rm_hi, o));
        }
        float nm_lo = fmaxf(m_lo, rm_lo), nm_hi = fmaxf(m_hi, rm_hi);
        float corr_lo = __expf(m_lo - nm_lo), corr_hi = __expf(m_hi - nm_hi);
        m_lo = nm_lo; m_hi = nm_hi;
        float rs_lo = 0.f, rs_hi = 0.f;
#pragma unroll
        for (int nt = 0; nt < 8; nt++) {
            s_acc[nt][0] = __expf(s_acc[nt][0] - nm_lo);
            s_acc[nt][1] = __expf(s_acc[nt][1] - nm_lo);
            s_acc[nt][2] = __expf(s_acc[nt][2] - nm_hi);
            s_acc[nt][3] = __expf(s_acc[nt][3] - nm_hi);
            rs_lo += s_acc[nt][0] + s_acc[nt][1];
            rs_hi += s_acc[nt][2] + s_acc[nt][3];
        }
#pragma unroll
        for (int o = 1; o < 4; o <<= 1) {
            rs_lo += __shfl_xor_sync(0xffffffffu, rs_lo, o);
            rs_hi += __shfl_xor_sync(0xffffffffu, rs_hi, o);
        }
        l_lo = l_lo * corr_lo + rs_lo;
        l_hi = l_hi * corr_hi + rs_hi;
#pragma unroll
        for (int nt = 0; nt < 16; nt++) {
            o_acc[nt][0] *= corr_lo; o_acc[nt][1] *= corr_lo;
            o_acc[nt][2] *= corr_hi; o_acc[nt][3] *= corr_hi;
        }

        // ---- O += P V ----
#pragma unroll
        for (int kc2 = 0; kc2 < 4; kc2++) {
            uint32_t p[4];
            p[0] = pack_h2(s_acc[2 * kc2][0],     s_acc[2 * kc2][1]);
            p[1] = pack_h2(s_acc[2 * kc2][2],     s_acc[2 * kc2][3]);
            p[2] = pack_h2(s_acc[2 * kc2 + 1][0], s_acc[2 * kc2 + 1][1]);
            p[3] = pack_h2(s_acc[2 * kc2 + 1][2], s_acc[2 * kc2 + 1][3]);
#pragma unroll
            for (int nd = 0; nd < 8; nd++) {
                uint32_t vh[4];
                ldsm4t(vh[0], vh[1], vh[2], vh[3],
                       st + KVM + (16 * kc2 + v_row) * AROW + nd * 32 + v_cb);
                mma16816(o_acc[2 * nd],     p, &vh[0]);
                mma16816(o_acc[2 * nd + 1], p, &vh[2]);
            }
        }
        __syncthreads();
    }

    // ---- epilogue: normalize + store y as fp16 ----
    float inv_lo = 1.0f / l_lo, inv_hi = 1.0f / l_hi;
    int row_lo = q0 + 16 * wq + r_lo;
#pragma unroll
    for (int nt = 0; nt < 16; nt++) {
        int col = h * HD + 8 * nt + 2 * (lane & 3);
        size_t off_lo = (size_t)(b * SEQ + row_lo) * NE + col;
        size_t off_hi = (size_t)(b * SEQ + row_lo + 8) * NE + col;
        *(uint32_t*)&g_yh[off_lo] = pack_h2(o_acc[nt][0] * inv_lo, o_acc[nt][1] * inv_lo);
        *(uint32_t*)&g_yh[off_hi] = pack_h2(o_acc[nt][2] * inv_hi, o_acc[nt][3] * inv_hi);
    }
}

// ==========================================================================
extern "C" void kernel_launch(void* const* d_in, const int* in_sizes, int n_in,
                              void* d_out, int out_size)
{
    const float* x   = (const float*)d_in[0];
    const float* Wq  = (const float*)d_in[1];
    const float* Wk  = (const float*)d_in[2];
    const float* Wv  = (const float*)d_in[3];
    const float* Wo  = (const float*)d_in[4];
    const int*   pos = (const int*)d_in[5];
    float* out = (float*)d_out;

    fill_rope_kernel<<<(SEQ * 64 + 255) / 256, 256>>>(pos);
    conv_all_kernel<<<(N4ALL + 255) / 256, 256>>>(x, Wq, Wk, Wv, Wo);

    const int gsmem = NPIPE * STGB;   // 165888
    cudaFuncSetAttribute(gemm_kernel<0>,
                         cudaFuncAttributeMaxDynamicSharedMemorySize, gsmem);
    cudaFuncSetAttribute(gemm_kernel<1>,
                         cudaFuncAttributeMaxDynamicSharedMemorySize, gsmem);

    // QKV projection: N = 3072 -> 12 tiles of 256; M = 4096 -> 32 tiles
    gemm_kernel<0><<<dim3(12, 32), 256, gsmem>>>(0, nullptr);

    // attention (tensor-core, single fp16, occupancy 2)
    cudaFuncSetAttribute(attn_kernel,
                         cudaFuncAttributeMaxDynamicSharedMemorySize, ATT_SMEM);
    attn_kernel<<<dim3(SEQ / 128, BATCH * NH), 256, ATT_SMEM>>>(pos);

    // output projection: N = 2048 -> 8 tiles of 256; M = 4096 -> 32 tiles
    gemm_kernel<1><<<dim3(8, 32), 256, gsmem>>>(NQKV, out);
}

// round 8
// speedup vs baseline: 6.9930x; 1.0210x over previous
#include <cuda_runtime.h>
#include <cuda_fp16.h>
#include <cstdint>

#define NE    2048
#define NH    16
#define NKV   4
#define HD    128
#define SEQ   2048
#define BATCH 2
#define MTOT  (BATCH * SEQ)                 // 4096
#define NQKV  (NH * HD + 2 * NKV * HD)      // 3072

#define ROPE_L2 0.10381025296522976f
#define SC 0.08838834764831845f             // 1/sqrt(128)
// Q pre-scale includes log2(e): scores come out in log2 domain
#define SCL2 (0.08838834764831845f * 1.4426950408889634f)

// -------------------- device scratch (all single fp16) --------------------
__device__ float2 g_rope[SEQ * 64];

__device__ __half g_xh[(size_t)MTOT * NE];
__device__ __half g_wh[(size_t)(NQKV + NE) * NE];   // Wq|Wk|Wv|Wo rows
__device__ __half g_yh[(size_t)MTOT * NE];

__device__ __half g_qh[(size_t)BATCH * NH * SEQ * HD];
__device__ __half g_kh[(size_t)BATCH * NKV * SEQ * HD];
__device__ __half g_vh[(size_t)BATCH * NKV * SEQ * HD];

// -------------------- PTX helpers (plain-target only) --------------------
__device__ __forceinline__ uint32_t cvta_smem(const void* p) {
    uint32_t a;
    asm("{ .reg .u64 t; cvta.to.shared.u64 t, %1; cvt.u32.u64 %0, t; }"
        : "=r"(a) : "l"(p));
    return a;
}
__device__ __forceinline__ void cp16(uint32_t dst, const void* src) {
    asm volatile("cp.async.cg.shared.global [%0], [%1], 16;" :: "r"(dst), "l"(src));
}
__device__ __forceinline__ void cp_commit() {
    asm volatile("cp.async.commit_group;" ::: "memory");
}
template <int N>
__device__ __forceinline__ void cp_wait() {
    asm volatile("cp.async.wait_group %0;" :: "n"(N) : "memory");
}
__device__ __forceinline__ void ldsm4(uint32_t& r0, uint32_t& r1,
                                      uint32_t& r2, uint32_t& r3, uint32_t a) {
    asm volatile("ldmatrix.sync.aligned.m8n8.x4.shared.b16 {%0,%1,%2,%3}, [%4];"
                 : "=r"(r0), "=r"(r1), "=r"(r2), "=r"(r3) : "r"(a));
}
__device__ __forceinline__ void ldsm4t(uint32_t& r0, uint32_t& r1,
                                       uint32_t& r2, uint32_t& r3, uint32_t a) {
    asm volatile("ldmatrix.sync.aligned.m8n8.x4.trans.shared.b16 {%0,%1,%2,%3}, [%4];"
                 : "=r"(r0), "=r"(r1), "=r"(r2), "=r"(r3) : "r"(a));
}
__device__ __forceinline__ void mma16816(float* c, const uint32_t* a,
                                         const uint32_t* b) {
    asm volatile(
        "mma.sync.aligned.m16n8k16.row.col.f32.f16.f16.f32 "
        "{%0,%1,%2,%3}, {%4,%5,%6,%7}, {%8,%9}, {%0,%1,%2,%3};"
        : "+f"(c[0]), "+f"(c[1]), "+f"(c[2]), "+f"(c[3])
        : "r"(a[0]), "r"(a[1]), "r"(a[2]), "r"(a[3]), "r"(b[0]), "r"(b[1]));
}

__device__ __forceinline__ uint32_t pack_h2(float a, float b) {
    __half2 h = __floats2half2_rn(a, b);
    return *(uint32_t*)&h;
}

// -------------------- merged prep kernel: rope table + fp32->fp16 ---------
#define N4X (MTOT * NE / 4)                 // 2097152
#define N4Q (NH * HD * NE / 4)              // 1048576
#define N4K (NKV * HD * NE / 4)             // 262144
#define N4ALL (N4X + 2 * N4Q + 2 * N4K)     // 4718592
#define ROPE_BLOCKS ((SEQ * 64) / 256)      // 512

__global__ void prep_kernel(const float* __restrict__ x,
                            const float* __restrict__ Wq,
                            const float* __restrict__ Wk,
                            const float* __restrict__ Wv,
                            const float* __restrict__ Wo,
                            const int* __restrict__ pos_ids)
{
    int bid = blockIdx.x;
    if (bid < ROPE_BLOCKS) {
        int idx = bid * 256 + threadIdx.x;
        int s = idx >> 6, p = idx & 63;
        float pos = (float)pos_ids[s];
        float f = pos * exp2f(-(float)(2 * p) * ROPE_L2);
        float sn, cs;
        sincosf(f, &sn, &cs);
        g_rope[idx] = make_float2(cs, sn);
        return;
    }
    int i = (bid - ROPE_BLOCKS) * 256 + threadIdx.x;
    if (i >= N4ALL) return;
    const float4* src;
    uint2* dst;
    if (i < N4X) {
        src = (const float4*)x + i;
        dst = (uint2*)g_xh + i;
    } else {
        int j = i - N4X;
        if (j < N4Q) {
            src = (const float4*)Wq + j;
        } else if (j < N4Q + N4K) {
            src = (const float4*)Wk + (j - N4Q);
        } else if (j < N4Q + 2 * N4K) {
            src = (const float4*)Wv + (j - N4Q - N4K);
        } else {
            src = (const float4*)Wo + (j - N4Q - 2 * N4K);
        }
        dst = (uint2*)g_wh + j;
    }
    float4 v = *src;
    *dst = make_uint2(pack_h2(v.x, v.y), pack_h2(v.z, v.w));
}

// ==========================================================================
// single-fp16 tensor-core GEMM:  C[m,n] = sum_k A[m,k] * W[n,k]
// CTA tile 128x128, 128 threads (4 warps, 2x2), warp tile 64x64.
// K-chunk 64, 3-stage cp.async pipeline, rows padded to 144B.
// Occupancy 2 (110592B smem/CTA, 128-thread CTA -> no register cap).
// MODE 0: A = g_xh, RoPE + scatter fp16 to q/k/v (Q pre-scaled by SCL2)
// MODE 1: A = g_yh, fp32 store to outp
// ==========================================================================
#define KCH     64
#define NSTG    (NE / KCH)       // 32
#define ROWB    144              // 128B data + 16B pad
#define MATA    (128 * ROWB)     // 18432
#define STGB    (2 * MATA)       // 36864 per stage: A | B
#define NPIPE   3

template <int MODE>
__global__ __launch_bounds__(128, 2)
void gemm_kernel(int browbase, float* __restrict__ outp)
{
    extern __shared__ char smem[];
    const uint32_t sb = cvta_smem(smem);
    const int tid  = threadIdx.x;
    const int wid  = tid >> 5, lane = tid & 31;
    const int wm   = (wid >> 1) * 64;        // warp m-offset (0 or 64)
    const int wn   = (wid & 1) * 64;         // warp n-offset (0 or 64)
    const int bn   = blockIdx.x * 128;
    const int bm   = blockIdx.y * 128;

    const __half* A = (MODE == 0) ? g_xh : g_yh;

    float acc[4][8][4];
#pragma unroll
    for (int f = 0; f < 4; f++)
#pragma unroll
        for (int n = 0; n < 8; n++)
#pragma unroll
            for (int q = 0; q < 4; q++) acc[f][n][q] = 0.f;

    // loads: A 128 rows x 8 chunks, B 128 rows x 8 chunks; 16 cp16/thread
    const int lrow = tid >> 3;               // 0..15
    const int lch  = tid & 7;                // chunk 0..7

    const uint32_t aoff = (uint32_t)((wm + (lane & 15)) * ROWB + (lane >> 4) * 16);
    const uint32_t boff = (uint32_t)(MATA
        + (wn + (lane & 7) + ((lane >> 4) << 3)) * ROWB
        + ((lane >> 3) & 1) * 16);

    auto issue = [&](int s) {
        const uint32_t st = sb + (s % NPIPE) * STGB;
        const size_t ko = (size_t)s * KCH + lch * 8;
#pragma unroll
        for (int it = 0; it < 8; it++) {
            int r = lrow + it * 16;
            cp16(st + r * ROWB + lch * 16, A + (size_t)(bm + r) * NE + ko);
            cp16(st + MATA + r * ROWB + lch * 16,
                 g_wh + (size_t)(browbase + bn + r) * NE + ko);
        }
        cp_commit();
    };

    issue(0);
    issue(1);

    for (int s = 0; s < NSTG; s++) {
        if (s + 2 < NSTG) { issue(s + 2); cp_wait<2>(); }
        else if (s + 1 < NSTG) cp_wait<1>();
        else cp_wait<0>();
        __syncthreads();

        const uint32_t st = sb + (s % NPIPE) * STGB;
#pragma unroll
        for (int t = 0; t < 4; t++) {
            uint32_t bh[16];
#pragma unroll
            for (int g = 0; g < 4; g++)
                ldsm4(bh[g * 4 + 0], bh[g * 4 + 1], bh[g * 4 + 2], bh[g * 4 + 3],
                      st + boff + g * 16 * ROWB + t * 32);
#pragma unroll
            for (int f = 0; f < 4; f++) {
                uint32_t ah[4];
                ldsm4(ah[0], ah[1], ah[2], ah[3],
                      st + aoff + f * 16 * ROWB + t * 32);
#pragma unroll
                for (int n = 0; n < 8; n++)
                    mma16816(acc[f][n], ah, &bh[n * 2]);
            }
        }
        __syncthreads();
    }

    const int r0 = lane >> 2;
    const int c0 = (lane & 3) * 2;

    if (MODE == 1) {
#pragma unroll
        for (int f = 0; f < 4; f++)
#pragma unroll
            for (int n = 0; n < 8; n++) {
                int m = bm + wm + f * 16 + r0;
                int c = bn + wn + n * 8 + c0;
                *(float2*)&outp[(size_t)m * NE + c] =
                    make_float2(acc[f][n][0], acc[f][n][1]);
                *(float2*)&outp[(size_t)(m + 8) * NE + c] =
                    make_float2(acc[f][n][2], acc[f][n][3]);
            }
    } else {
        // N-tiles of 128 are region-aligned (2048, 2560 are multiples of 128)
        const int region = (bn < NH * HD) ? 0 : ((bn < NH * HD + NKV * HD) ? 1 : 2);
#pragma unroll
        for (int f = 0; f < 4; f++)
#pragma unroll
            for (int n = 0; n < 8; n++) {
                int nglob = bn + wn + n * 8 + c0;
#pragma unroll
                for (int half = 0; half < 2; half++) {
                    int m = bm + wm + f * 16 + r0 + half * 8;
                    int bb = m >> 11, s = m & (SEQ - 1);
                    float v0 = acc[f][n][half * 2 + 0];
                    float v1 = acc[f][n][half * 2 + 1];
                    if (region == 2) {
                        int nl = nglob - NH * HD - NKV * HD;
                        int h = nl >> 7, d0 = nl & 127;
                        size_t off = (((size_t)(bb * NKV + h)) * SEQ + s) * HD + d0;
                        *(uint32_t*)&g_vh[off] = pack_h2(v0, v1);
                    } else {
                        int nl = (region == 0) ? nglob : (nglob - NH * HD);
                        int h = nl >> 7, d0 = nl & 127;
                        float2 cs = g_rope[s * 64 + (d0 >> 1)];
                        float ox = v0 * cs.x - v1 * cs.y;
                        float oy = v1 * cs.x + v0 * cs.y;
                        if (region == 0) {
                            ox *= SCL2; oy *= SCL2;   // includes log2(e)
                            size_t off = (((size_t)(bb * NH + h)) * SEQ + s) * HD + d0;
                            *(uint32_t*)&g_qh[off] = pack_h2(ox, oy);
                        } else {
                            size_t off = (((size_t)(bb * NKV + h)) * SEQ + s) * HD + d0;
                            *(uint32_t*)&g_kh[off] = pack_h2(ox, oy);
                        }
                    }
                }
            }
    }
}

// ==========================================================================
// Tensor-core flash attention, single-fp16 operands, fp32 accum.
// Scores in log2 domain (Q pre-scaled by SC*log2e); exp2f softmax;
// vote-gated o_acc rescale. Occupancy 2.
// ==========================================================================
#define AROW   272
#define QTB    (128 * AROW)             // 34816
#define KVM    (64 * AROW)              // 17408
#define KVSTG  (2 * KVM)                // 34816 per stage: K | V
#define ATT_SMEM (QTB + 2 * KVSTG)      // 104448

__global__ void __launch_bounds__(256, 2)
attn_kernel(const int* __restrict__ pos_ids)
{
    extern __shared__ char smem[];
    const uint32_t sb = cvta_smem(smem);
    const int tid = threadIdx.x;
    const int lane = tid & 31, wq = tid >> 5;
    const int qt = gridDim.x - 1 - blockIdx.x;   // heavy tiles first
    const int bh = blockIdx.y;
    const int b = bh >> 4, h = bh & 15, kvh = h >> 2;
    const int q0 = qt * 128;

    const size_t qbase = (((size_t)(b * NH + h)) * SEQ + q0) * HD;
    const size_t kvbase = ((size_t)(b * NKV + kvh)) * SEQ * HD;

    // ---- load Q ----
#pragma unroll
    for (int it = 0; it < 8; it++) {
        int rem = it * 256 + tid;
        int row = rem >> 4, ch = rem & 15;
        cp16(sb + row * AROW + ch * 16,
             g_qh + qbase + (size_t)row * HD + ch * 8);
    }
    cp_commit();

    const int nkt = 2 * qt + 2;

    auto issue_kv = [&](int kt) {
        const uint32_t st = sb + QTB + (kt & 1) * KVSTG;
        const int k0 = kt * 64;
#pragma unroll
        for (int it = 0; it < 8; it++) {
            int mat = it >> 2;
            int rem = (it & 3) * 256 + tid;
            int row = rem >> 4, ch = rem & 15;
            const __half* base = mat ? g_vh : g_kh;
            cp16(st + mat * KVM + row * AROW + ch * 16,
                 base + kvbase + (size_t)(k0 + row) * HD + ch * 8);
        }
        cp_commit();
    };

    issue_kv(0);

    float m_lo = -1e30f, m_hi = -1e30f, l_lo = 0.f, l_hi = 0.f;
    float o_acc[16][4];
#pragma unroll
    for (int nt = 0; nt < 16; nt++)
#pragma unroll
        for (int j = 0; j < 4; j++) o_acc[nt][j] = 0.f;

    const int r_lo = lane >> 2;
    const int pq_lo = pos_ids[q0 + 16 * wq + r_lo];
    const int pq_hi = pos_ids[q0 + 16 * wq + r_lo + 8];

    const uint32_t q_a = sb + (16 * wq + (lane & 15)) * AROW + (lane >> 4) * 16;
    const uint32_t k_row = (lane & 7) + ((lane >> 4) << 3);
    const uint32_t k_cb  = ((lane >> 3) & 1) * 16;
    const uint32_t v_row = (lane & 7) + (((lane >> 3) & 1) << 3);
    const uint32_t v_cb  = (lane >> 4) * 16;

    for (int kt = 0; kt < nkt; kt++) {
        if (kt + 1 < nkt) { issue_kv(kt + 1); cp_wait<1>(); }
        else cp_wait<0>();
        __syncthreads();
        const uint32_t st = sb + QTB + (kt & 1) * KVSTG;
        const int k0 = kt * 64;

        // ---- S = Q K^T (log2 domain) ----
        float s_acc[8][4];
#pragma unroll
        for (int nt = 0; nt < 8; nt++)
#pragma unroll
            for (int j = 0; j < 4; j++) s_acc[nt][j] = 0.f;

#pragma unroll
        for (int kc = 0; kc < 8; kc++) {
            uint32_t ah[4];
            ldsm4(ah[0], ah[1], ah[2], ah[3], q_a + kc * 32);
#pragma unroll
            for (int kp = 0; kp < 4; kp++) {
                uint32_t kh[4];
                ldsm4(kh[0], kh[1], kh[2], kh[3],
                      st + (16 * kp + k_row) * AROW + kc * 32 + k_cb);
                mma16816(s_acc[2 * kp],     ah, &kh[0]);
                mma16816(s_acc[2 * kp + 1], ah, &kh[2]);
            }
        }

        // ---- causal mask ----
        if (k0 + 63 > pq_lo) {
#pragma unroll
            for (int nt = 0; nt < 8; nt++) {
                int c = k0 + 8 * nt + 2 * (lane & 3);
                if (c     > pq_lo) s_acc[nt][0] = -1e30f;
                if (c + 1 > pq_lo) s_acc[nt][1] = -1e30f;
                if (c     > pq_hi) s_acc[nt][2] = -1e30f;
                if (c + 1 > pq_hi) s_acc[nt][3] = -1e30f;
            }
        }

        // ---- online softmax (base-2) ----
        float rm_lo = -1e30f, rm_hi = -1e30f;
#pragma unroll
        for (int nt = 0; nt < 8; nt++) {
            rm_lo = fmaxf(rm_lo, fmaxf(s_acc[nt][0], s_acc[nt][1]));
            rm_hi = fmaxf(rm_hi, fmaxf(s_acc[nt][2], s_acc[nt][3]));
        }
#pragma unroll
        for (int o = 1; o < 4; o <<= 1) {
            rm_lo = fmaxf(rm_lo, __shfl_xor_sync(0xffffffffu, rm_lo, o));
            rm_hi = fmaxf(rm_hi, __shfl_xor_sync(0xffffffffu, rm_hi, o));
        }
        bool need = (rm_lo > m_lo) || (rm_hi > m_hi);
        float nm_lo = fmaxf(m_lo, rm_lo), nm_hi = fmaxf(m_hi, rm_hi);
        float corr_lo = exp2f(m_lo - nm_lo), corr_hi = exp2f(m_hi - nm_hi);
        m_lo = nm_lo; m_hi = nm_hi;
        float rs_lo = 0.f, rs_hi = 0.f;
#pragma unroll
        for (int nt = 0; nt < 8; nt++) {
            s_acc[nt][0] = exp2f(s_acc[nt][0] - nm_lo);
            s_acc[nt][1] = exp2f(s_acc[nt][1] - nm_lo);
            s_acc[nt][2] = exp2f(s_acc[nt][2] - nm_hi);
            s_acc[nt][3] = exp2f(s_acc[nt][3] - nm_hi);
            rs_lo += s_acc[nt][0] + s_acc[nt][1];
            rs_hi += s_acc[nt][2] + s_acc[nt][3];
        }
#pragma unroll
        for (int o = 1; o < 4; o <<= 1) {
            rs_lo += __shfl_xor_sync(0xffffffffu, rs_lo, o);
            rs_hi += __shfl_xor_sync(0xffffffffu, rs_hi, o);
        }
        l_lo = l_lo * corr_lo + rs_lo;
        l_hi = l_hi * corr_hi + rs_hi;
        if (__any_sync(0xffffffffu, need)) {
#pragma unroll
            for (int nt = 0; nt < 16; nt++) {
                o_acc[nt][0] *= corr_lo; o_acc[nt][1] *= corr_lo;
                o_acc[nt][2] *= corr_hi; o_acc[nt][3] *= corr_hi;
            }
        }

        // ---- O += P V ----
#pragma unroll
        for (int kc2 = 0; kc2 < 4; kc2++) {
            uint32_t p[4];
            p[0] = pack_h2(s_acc[2 * kc2][0],     s_acc[2 * kc2][1]);
            p[1] = pack_h2(s_acc[2 * kc2][2],     s_acc[2 * kc2][3]);
            p[2] = pack_h2(s_acc[2 * kc2 + 1][0], s_acc[2 * kc2 + 1][1]);
            p[3] = pack_h2(s_acc[2 * kc2 + 1][2], s_acc[2 * kc2 + 1][3]);
#pragma unroll
            for (int nd = 0; nd < 8; nd++) {
                uint32_t vh[4];
                ldsm4t(vh[0], vh[1], vh[2], vh[3],
                       st + KVM + (16 * kc2 + v_row) * AROW + nd * 32 + v_cb);
                mma16816(o_acc[2 * nd],     p, &vh[0]);
                mma16816(o_acc[2 * nd + 1], p, &vh[2]);
            }
        }
        __syncthreads();
    }

    // ---- epilogue: normalize + store y as fp16 ----
    float inv_lo = 1.0f / l_lo, inv_hi = 1.0f / l_hi;
    int row_lo = q0 + 16 * wq + r_lo;
#pragma unroll
    for (int nt = 0; nt < 16; nt++) {
        int col = h * HD + 8 * nt + 2 * (lane & 3);
        size_t off_lo = (size_t)(b * SEQ + row_lo) * NE + col;
        size_t off_hi = (size_t)(b * SEQ + row_lo + 8) * NE + col;
        *(uint32_t*)&g_yh[off_lo] = pack_h2(o_acc[nt][0] * inv_lo, o_acc[nt][1] * inv_lo);
        *(uint32_t*)&g_yh[off_hi] = pack_h2(o_acc[nt][2] * inv_hi, o_acc[nt][3] * inv_hi);
    }
}

// ==========================================================================
extern "C" void kernel_launch(void* const* d_in, const int* in_sizes, int n_in,
                              void* d_out, int out_size)
{
    const float* x   = (const float*)d_in[0];
    const float* Wq  = (const float*)d_in[1];
    const float* Wk  = (const float*)d_in[2];
    const float* Wv  = (const float*)d_in[3];
    const float* Wo  = (const float*)d_in[4];
    const int*   pos = (const int*)d_in[5];
    float* out = (float*)d_out;

    // rope table + fp16 conversions, one launch
    prep_kernel<<<ROPE_BLOCKS + (N4ALL + 255) / 256, 256>>>(x, Wq, Wk, Wv, Wo, pos);

    const int gsmem = NPIPE * STGB;   // 110592 -> occupancy 2
    cudaFuncSetAttribute(gemm_kernel<0>,
                         cudaFuncAttributeMaxDynamicSharedMemorySize, gsmem);
    cudaFuncSetAttribute(gemm_kernel<1>,
                         cudaFuncAttributeMaxDynamicSharedMemorySize, gsmem);

    // QKV projection: N = 3072 -> 24 tiles of 128; M = 4096 -> 32 tiles
    gemm_kernel<0><<<dim3(24, 32), 128, gsmem>>>(0, nullptr);

    // attention (tensor-core, single fp16, occupancy 2)
    cudaFuncSetAttribute(attn_kernel,
                         cudaFuncAttributeMaxDynamicSharedMemorySize, ATT_SMEM);
    attn_kernel<<<dim3(SEQ / 128, BATCH * NH), 256, ATT_SMEM>>>(pos);

    // output projection: N = 2048 -> 16 tiles of 128; M = 4096 -> 32 tiles
    gemm_kernel<1><<<dim3(16, 32), 128, gsmem>>>(NQKV, out);
}

// round 9
// speedup vs baseline: 7.3285x; 1.0480x over previous
#include <cuda_runtime.h>
#include <cuda_fp16.h>
#include <cstdint>

#define NE    2048
#define NH    16
#define NKV   4
#define HD    128
#define SEQ   2048
#define BATCH 2
#define MTOT  (BATCH * SEQ)                 // 4096
#define NQKV  (NH * HD + 2 * NKV * HD)      // 3072

#define ROPE_L2 0.10381025296522976f
#define SC 0.08838834764831845f             // 1/sqrt(128)
#define SCL2 (0.08838834764831845f * 1.4426950408889634f)

// -------------------- device scratch (all single fp16) --------------------
__device__ float2 g_rope[SEQ * 64];

__device__ __half g_xh[(size_t)MTOT * NE];
__device__ __half g_wh[(size_t)(NQKV + NE) * NE];   // Wq|Wk|Wv|Wo rows
__device__ __half g_yh[(size_t)MTOT * NE];

__device__ __half g_qh[(size_t)BATCH * NH * SEQ * HD];
__device__ __half g_kh[(size_t)BATCH * NKV * SEQ * HD];
__device__ __half g_vh[(size_t)BATCH * NKV * SEQ * HD];

// -------------------- PTX helpers (plain-target only) --------------------
__device__ __forceinline__ uint32_t cvta_smem(const void* p) {
    uint32_t a;
    asm("{ .reg .u64 t; cvta.to.shared.u64 t, %1; cvt.u32.u64 %0, t; }"
        : "=r"(a) : "l"(p));
    return a;
}
__device__ __forceinline__ void cp16(uint32_t dst, const void* src) {
    asm volatile("cp.async.cg.shared.global [%0], [%1], 16;" :: "r"(dst), "l"(src));
}
__device__ __forceinline__ void cp_commit() {
    asm volatile("cp.async.commit_group;" ::: "memory");
}
template <int N>
__device__ __forceinline__ void cp_wait() {
    asm volatile("cp.async.wait_group %0;" :: "n"(N) : "memory");
}
__device__ __forceinline__ void ldsm4(uint32_t& r0, uint32_t& r1,
                                      uint32_t& r2, uint32_t& r3, uint32_t a) {
    asm volatile("ldmatrix.sync.aligned.m8n8.x4.shared.b16 {%0,%1,%2,%3}, [%4];"
                 : "=r"(r0), "=r"(r1), "=r"(r2), "=r"(r3) : "r"(a));
}
__device__ __forceinline__ void ldsm4t(uint32_t& r0, uint32_t& r1,
                                       uint32_t& r2, uint32_t& r3, uint32_t a) {
    asm volatile("ldmatrix.sync.aligned.m8n8.x4.trans.shared.b16 {%0,%1,%2,%3}, [%4];"
                 : "=r"(r0), "=r"(r1), "=r"(r2), "=r"(r3) : "r"(a));
}
__device__ __forceinline__ void mma16816(float* c, const uint32_t* a,
                                         const uint32_t* b) {
    asm volatile(
        "mma.sync.aligned.m16n8k16.row.col.f32.f16.f16.f32 "
        "{%0,%1,%2,%3}, {%4,%5,%6,%7}, {%8,%9}, {%0,%1,%2,%3};"
        : "+f"(c[0]), "+f"(c[1]), "+f"(c[2]), "+f"(c[3])
        : "r"(a[0]), "r"(a[1]), "r"(a[2]), "r"(a[3]), "r"(b[0]), "r"(b[1]));
}

__device__ __forceinline__ uint32_t pack_h2(float a, float b) {
    __half2 h = __floats2half2_rn(a, b);
    return *(uint32_t*)&h;
}

// -------------------- merged prep kernel: rope table + fp32->fp16 ---------
#define N4X (MTOT * NE / 4)                 // 2097152
#define N4Q (NH * HD * NE / 4)              // 1048576
#define N4K (NKV * HD * NE / 4)             // 262144
#define N4ALL (N4X + 2 * N4Q + 2 * N4K)     // 4718592
#define ROPE_BLOCKS ((SEQ * 64) / 256)      // 512

__global__ void prep_kernel(const float* __restrict__ x,
                            const float* __restrict__ Wq,
                            const float* __restrict__ Wk,
                            const float* __restrict__ Wv,
                            const float* __restrict__ Wo,
                            const int* __restrict__ pos_ids)
{
    int bid = blockIdx.x;
    if (bid < ROPE_BLOCKS) {
        int idx = bid * 256 + threadIdx.x;
        int s = idx >> 6, p = idx & 63;
        float pos = (float)pos_ids[s];
        float f = pos * exp2f(-(float)(2 * p) * ROPE_L2);
        float sn, cs;
        sincosf(f, &sn, &cs);
        g_rope[idx] = make_float2(cs, sn);
        return;
    }
    int i = (bid - ROPE_BLOCKS) * 256 + threadIdx.x;
    if (i >= N4ALL) return;
    const float4* src;
    uint2* dst;
    if (i < N4X) {
        src = (const float4*)x + i;
        dst = (uint2*)g_xh + i;
    } else {
        int j = i - N4X;
        if (j < N4Q) {
            src = (const float4*)Wq + j;
        } else if (j < N4Q + N4K) {
            src = (const float4*)Wk + (j - N4Q);
        } else if (j < N4Q + 2 * N4K) {
            src = (const float4*)Wv + (j - N4Q - N4K);
        } else {
            src = (const float4*)Wo + (j - N4Q - 2 * N4K);
        }
        dst = (uint2*)g_wh + j;
    }
    float4 v = *src;
    *dst = make_uint2(pack_h2(v.x, v.y), pack_h2(v.z, v.w));
}

// ==========================================================================
// single-fp16 tensor-core GEMM:  C[m,n] = sum_k A[m,k] * W[n,k]
// CTA tile 128x128, 256 threads (8 warps, 2x4), warp tile 64x32.
// K-chunk 64, 3-stage cp.async pipeline, rows padded to 144B.
// Occupancy 2 (110592B smem/CTA, 128-reg cap) -> 16 warps/SM, 4 per SMSP.
// MODE 0: A = g_xh, RoPE + scatter fp16 to q/k/v (Q pre-scaled by SCL2)
// MODE 1: A = g_yh, fp32 store to outp
// ==========================================================================
#define KCH     64
#define NSTG    (NE / KCH)       // 32
#define ROWB    144              // 128B data + 16B pad
#define MATA    (128 * ROWB)     // 18432
#define STGB    (2 * MATA)       // 36864 per stage: A | B
#define NPIPE   3

template <int MODE>
__global__ __launch_bounds__(256, 2)
void gemm_kernel(int browbase, float* __restrict__ outp)
{
    extern __shared__ char smem[];
    const uint32_t sb = cvta_smem(smem);
    const int tid  = threadIdx.x;
    const int wid  = tid >> 5, lane = tid & 31;
    const int wm   = (wid >> 2) * 64;        // warp m-offset (0 or 64)
    const int wn   = (wid & 3) * 32;         // warp n-offset (0,32,64,96)
    const int bn   = blockIdx.x * 128;
    const int bm   = blockIdx.y * 128;

    const __half* A = (MODE == 0) ? g_xh : g_yh;

    float acc[4][4][4];                      // 64 regs
#pragma unroll
    for (int f = 0; f < 4; f++)
#pragma unroll
        for (int n = 0; n < 4; n++)
#pragma unroll
            for (int q = 0; q < 4; q++) acc[f][n][q] = 0.f;

    // loads: A 1024 + B 1024 16B-chunks; 256 threads -> 8 cp16/thread
    const int lrow = tid >> 3;               // 0..31
    const int lch  = tid & 7;                // chunk 0..7

    const uint32_t aoff = (uint32_t)((wm + (lane & 15)) * ROWB + (lane >> 4) * 16);
    const uint32_t boff = (uint32_t)(MATA
        + (wn + (lane & 7) + ((lane >> 4) << 3)) * ROWB
        + ((lane >> 3) & 1) * 16);

    auto issue = [&](int s) {
        const uint32_t st = sb + (s % NPIPE) * STGB;
        const size_t ko = (size_t)s * KCH + lch * 8;
#pragma unroll
        for (int it = 0; it < 4; it++) {
            int r = lrow + it * 32;
            cp16(st + r * ROWB + lch * 16, A + (size_t)(bm + r) * NE + ko);
            cp16(st + MATA + r * ROWB + lch * 16,
                 g_wh + (size_t)(browbase + bn + r) * NE + ko);
        }
        cp_commit();
    };

    issue(0);
    issue(1);

    for (int s = 0; s < NSTG; s++) {
        if (s + 2 < NSTG) { issue(s + 2); cp_wait<2>(); }
        else if (s + 1 < NSTG) cp_wait<1>();
        else cp_wait<0>();
        __syncthreads();

        const uint32_t st = sb + (s % NPIPE) * STGB;
#pragma unroll
        for (int t = 0; t < 4; t++) {
            uint32_t bh[8];
#pragma unroll
            for (int g = 0; g < 2; g++)
                ldsm4(bh[g * 4 + 0], bh[g * 4 + 1], bh[g * 4 + 2], bh[g * 4 + 3],
                      st + boff + g * 16 * ROWB + t * 32);
#pragma unroll
            for (int f = 0; f < 4; f++) {
                uint32_t ah[4];
                ldsm4(ah[0], ah[1], ah[2], ah[3],
                      st + aoff + f * 16 * ROWB + t * 32);
#pragma unroll
                for (int n = 0; n < 4; n++)
                    mma16816(acc[f][n], ah, &bh[n * 2]);
            }
        }
        __syncthreads();
    }

    const int r0 = lane >> 2;
    const int c0 = (lane & 3) * 2;

    if (MODE == 1) {
#pragma unroll
        for (int f = 0; f < 4; f++)
#pragma unroll
            for (int n = 0; n < 4; n++) {
                int m = bm + wm + f * 16 + r0;
                int c = bn + wn + n * 8 + c0;
                *(float2*)&outp[(size_t)m * NE + c] =
                    make_float2(acc[f][n][0], acc[f][n][1]);
                *(float2*)&outp[(size_t)(m + 8) * NE + c] =
                    make_float2(acc[f][n][2], acc[f][n][3]);
            }
    } else {
        // N-tiles of 128 are region-aligned (2048, 2560 are multiples of 128)
        const int region = (bn < NH * HD) ? 0 : ((bn < NH * HD + NKV * HD) ? 1 : 2);
#pragma unroll
        for (int f = 0; f < 4; f++)
#pragma unroll
            for (int n = 0; n < 4; n++) {
                int nglob = bn + wn + n * 8 + c0;
#pragma unroll
                for (int half = 0; half < 2; half++) {
                    int m = bm + wm + f * 16 + r0 + half * 8;
                    int bb = m >> 11, s = m & (SEQ - 1);
                    float v0 = acc[f][n][half * 2 + 0];
                    float v1 = acc[f][n][half * 2 + 1];
                    if (region == 2) {
                        int nl = nglob - NH * HD - NKV * HD;
                        int h = nl >> 7, d0 = nl & 127;
                        size_t off = (((size_t)(bb * NKV + h)) * SEQ + s) * HD + d0;
                        *(uint32_t*)&g_vh[off] = pack_h2(v0, v1);
                    } else {
                        int nl = (region == 0) ? nglob : (nglob - NH * HD);
                        int h = nl >> 7, d0 = nl & 127;
                        float2 cs = g_rope[s * 64 + (d0 >> 1)];
                        float ox = v0 * cs.x - v1 * cs.y;
                        float oy = v1 * cs.x + v0 * cs.y;
                        if (region == 0) {
                            ox *= SCL2; oy *= SCL2;   // includes log2(e)
                            size_t off = (((size_t)(bb * NH + h)) * SEQ + s) * HD + d0;
                            *(uint32_t*)&g_qh[off] = pack_h2(ox, oy);
                        } else {
                            size_t off = (((size_t)(bb * NKV + h)) * SEQ + s) * HD + d0;
                            *(uint32_t*)&g_kh[off] = pack_h2(ox, oy);
                        }
                    }
                }
            }
    }
}

// ==========================================================================
// Tensor-core flash attention, single-fp16 operands, fp32 accum.
// Scores in log2 domain; exp2f softmax; vote-gated rescale. Occupancy 2.
// ==========================================================================
#define AROW   272
#define QTB    (128 * AROW)             // 34816
#define KVM    (64 * AROW)              // 17408
#define KVSTG  (2 * KVM)                // 34816 per stage: K | V
#define ATT_SMEM (QTB + 2 * KVSTG)      // 104448

__global__ void __launch_bounds__(256, 2)
attn_kernel(const int* __restrict__ pos_ids)
{
    extern __shared__ char smem[];
    const uint32_t sb = cvta_smem(smem);
    const int tid = threadIdx.x;
    const int lane = tid & 31, wq = tid >> 5;
    const int qt = gridDim.x - 1 - blockIdx.x;   // heavy tiles first
    const int bh = blockIdx.y;
    const int b = bh >> 4, h = bh & 15, kvh = h >> 2;
    const int q0 = qt * 128;

    const size_t qbase = (((size_t)(b * NH + h)) * SEQ + q0) * HD;
    const size_t kvbase = ((size_t)(b * NKV + kvh)) * SEQ * HD;

    // ---- load Q ----
#pragma unroll
    for (int it = 0; it < 8; it++) {
        int rem = it * 256 + tid;
        int row = rem >> 4, ch = rem & 15;
        cp16(sb + row * AROW + ch * 16,
             g_qh + qbase + (size_t)row * HD + ch * 8);
    }
    cp_commit();

    const int nkt = 2 * qt + 2;

    auto issue_kv = [&](int kt) {
        const uint32_t st = sb + QTB + (kt & 1) * KVSTG;
        const int k0 = kt * 64;
#pragma unroll
        for (int it = 0; it < 8; it++) {
            int mat = it >> 2;
            int rem = (it & 3) * 256 + tid;
            int row = rem >> 4, ch = rem & 15;
            const __half* base = mat ? g_vh : g_kh;
            cp16(st + mat * KVM + row * AROW + ch * 16,
                 base + kvbase + (size_t)(k0 + row) * HD + ch * 8);
        }
        cp_commit();
    };

    issue_kv(0);

    float m_lo = -1e30f, m_hi = -1e30f, l_lo = 0.f, l_hi = 0.f;
    float o_acc[16][4];
#pragma unroll
    for (int nt = 0; nt < 16; nt++)
#pragma unroll
        for (int j = 0; j < 4; j++) o_acc[nt][j] = 0.f;

    const int r_lo = lane >> 2;
    const int pq_lo = pos_ids[q0 + 16 * wq + r_lo];
    const int pq_hi = pos_ids[q0 + 16 * wq + r_lo + 8];

    const uint32_t q_a = sb + (16 * wq + (lane & 15)) * AROW + (lane >> 4) * 16;
    const uint32_t k_row = (lane & 7) + ((lane >> 4) << 3);
    const uint32_t k_cb  = ((lane >> 3) & 1) * 16;
    const uint32_t v_row = (lane & 7) + (((lane >> 3) & 1) << 3);
    const uint32_t v_cb  = (lane >> 4) * 16;

    for (int kt = 0; kt < nkt; kt++) {
        if (kt + 1 < nkt) { issue_kv(kt + 1); cp_wait<1>(); }
        else cp_wait<0>();
        __syncthreads();
        const uint32_t st = sb + QTB + (kt & 1) * KVSTG;
        const int k0 = kt * 64;

        // ---- S = Q K^T (log2 domain) ----
        float s_acc[8][4];
#pragma unroll
        for (int nt = 0; nt < 8; nt++)
#pragma unroll
            for (int j = 0; j < 4; j++) s_acc[nt][j] = 0.f;

#pragma unroll
        for (int kc = 0; kc < 8; kc++) {
            uint32_t ah[4];
            ldsm4(ah[0], ah[1], ah[2], ah[3], q_a + kc * 32);
#pragma unroll
            for (int kp = 0; kp < 4; kp++) {
                uint32_t kh[4];
                ldsm4(kh[0], kh[1], kh[2], kh[3],
                      st + (16 * kp + k_row) * AROW + kc * 32 + k_cb);
                mma16816(s_acc[2 * kp],     ah, &kh[0]);
                mma16816(s_acc[2 * kp + 1], ah, &kh[2]);
            }
        }

        // ---- causal mask ----
        if (k0 + 63 > pq_lo) {
#pragma unroll
            for (int nt = 0; nt < 8; nt++) {
                int c = k0 + 8 * nt + 2 * (lane & 3);
                if (c     > pq_lo) s_acc[nt][0] = -1e30f;
                if (c + 1 > pq_lo) s_acc[nt][1] = -1e30f;
                if (c     > pq_hi) s_acc[nt][2] = -1e30f;
                if (c + 1 > pq_hi) s_acc[nt][3] = -1e30f;
            }
        }

        // ---- online softmax (base-2) ----
        float rm_lo = -1e30f, rm_hi = -1e30f;
#pragma unroll
        for (int nt = 0; nt < 8; nt++) {
            rm_lo = fmaxf(rm_lo, fmaxf(s_acc[nt][0], s_acc[nt][1]));
            rm_hi = fmaxf(rm_hi, fmaxf(s_acc[nt][2], s_acc[nt][3]));
        }
#pragma unroll
        for (int o = 1; o < 4; o <<= 1) {
            rm_lo = fmaxf(rm_lo, __shfl_xor_sync(0xffffffffu, rm_lo, o));
            rm_hi = fmaxf(rm_hi, __shfl_xor_sync(0xffffffffu, rm_hi, o));
        }
        bool need = (rm_lo > m_lo) || (rm_hi > m_hi);
        float nm_lo = fmaxf(m_lo, rm_lo), nm_hi = fmaxf(m_hi, rm_hi);
        float corr_lo = exp2f(m_lo - nm_lo), corr_hi = exp2f(m_hi - nm_hi);
        m_lo = nm_lo; m_hi = nm_hi;
        float rs_lo = 0.f, rs_hi = 0.f;
#pragma unroll
        for (int nt = 0; nt < 8; nt++) {
            s_acc[nt][0] = exp2f(s_acc[nt][0] - nm_lo);
            s_acc[nt][1] = exp2f(s_acc[nt][1] - nm_lo);
            s_acc[nt][2] = exp2f(s_acc[nt][2] - nm_hi);
            s_acc[nt][3] = exp2f(s_acc[nt][3] - nm_hi);
            rs_lo += s_acc[nt][0] + s_acc[nt][1];
            rs_hi += s_acc[nt][2] + s_acc[nt][3];
        }
#pragma unroll
        for (int o = 1; o < 4; o <<= 1) {
            rs_lo += __shfl_xor_sync(0xffffffffu, rs_lo, o);
            rs_hi += __shfl_xor_sync(0xffffffffu, rs_hi, o);
        }
        l_lo = l_lo * corr_lo + rs_lo;
        l_hi = l_hi * corr_hi + rs_hi;
        if (__any_sync(0xffffffffu, need)) {
#pragma unroll
            for (int nt = 0; nt < 16; nt++) {
                o_acc[nt][0] *= corr_lo; o_acc[nt][1] *= corr_lo;
                o_acc[nt][2] *= corr_hi; o_acc[nt][3] *= corr_hi;
            }
        }

        // ---- O += P V ----
#pragma unroll
        for (int kc2 = 0; kc2 < 4; kc2++) {
            uint32_t p[4];
            p[0] = pack_h2(s_acc[2 * kc2][0],     s_acc[2 * kc2][1]);
            p[1] = pack_h2(s_acc[2 * kc2][2],     s_acc[2 * kc2][3]);
            p[2] = pack_h2(s_acc[2 * kc2 + 1][0], s_acc[2 * kc2 + 1][1]);
            p[3] = pack_h2(s_acc[2 * kc2 + 1][2], s_acc[2 * kc2 + 1][3]);
#pragma unroll
            for (int nd = 0; nd < 8; nd++) {
                uint32_t vh[4];
                ldsm4t(vh[0], vh[1], vh[2], vh[3],
                       st + KVM + (16 * kc2 + v_row) * AROW + nd * 32 + v_cb);
                mma16816(o_acc[2 * nd],     p, &vh[0]);
                mma16816(o_acc[2 * nd + 1], p, &vh[2]);
            }
        }
        __syncthreads();
    }

    // ---- epilogue: normalize + store y as fp16 ----
    float inv_lo = 1.0f / l_lo, inv_hi = 1.0f / l_hi;
    int row_lo = q0 + 16 * wq + r_lo;
#pragma unroll
    for (int nt = 0; nt < 16; nt++) {
        int col = h * HD + 8 * nt + 2 * (lane & 3);
        size_t off_lo = (size_t)(b * SEQ + row_lo) * NE + col;
        size_t off_hi = (size_t)(b * SEQ + row_lo + 8) * NE + col;
        *(uint32_t*)&g_yh[off_lo] = pack_h2(o_acc[nt][0] * inv_lo, o_acc[nt][1] * inv_lo);
        *(uint32_t*)&g_yh[off_hi] = pack_h2(o_acc[nt][2] * inv_hi, o_acc[nt][3] * inv_hi);
    }
}

// ==========================================================================
extern "C" void kernel_launch(void* const* d_in, const int* in_sizes, int n_in,
                              void* d_out, int out_size)
{
    const float* x   = (const float*)d_in[0];
    const float* Wq  = (const float*)d_in[1];
    const float* Wk  = (const float*)d_in[2];
    const float* Wv  = (const float*)d_in[3];
    const float* Wo  = (const float*)d_in[4];
    const int*   pos = (const int*)d_in[5];
    float* out = (float*)d_out;

    // rope table + fp16 conversions, one launch
    prep_kernel<<<ROPE_BLOCKS + (N4ALL + 255) / 256, 256>>>(x, Wq, Wk, Wv, Wo, pos);

    const int gsmem = NPIPE * STGB;   // 110592 -> occupancy 2
    cudaFuncSetAttribute(gemm_kernel<0>,
                         cudaFuncAttributeMaxDynamicSharedMemorySize, gsmem);
    cudaFuncSetAttribute(gemm_kernel<1>,
                         cudaFuncAttributeMaxDynamicSharedMemorySize, gsmem);

    // QKV projection: N = 3072 -> 24 tiles of 128; M = 4096 -> 32 tiles
    gemm_kernel<0><<<dim3(24, 32), 256, gsmem>>>(0, nullptr);

    // attention (tensor-core, single fp16, occupancy 2)
    cudaFuncSetAttribute(attn_kernel,
                         cudaFuncAttributeMaxDynamicSharedMemorySize, ATT_SMEM);
    attn_kernel<<<dim3(SEQ / 128, BATCH * NH), 256, ATT_SMEM>>>(pos);

    // output projection: N = 2048 -> 16 tiles of 128; M = 4096 -> 32 tiles
    gemm_kernel<1><<<dim3(16, 32), 256, gsmem>>>(NQKV, out);
}

// round 10
// speedup vs baseline: 7.6246x; 1.0404x over previous
#include <cuda_runtime.h>
#include <cuda_fp16.h>
#include <cstdint>

#define NE    2048
#define NH    16
#define NKV   4
#define HD    128
#define SEQ   2048
#define BATCH 2
#define MTOT  (BATCH * SEQ)                 // 4096
#define NQKV  (NH * HD + 2 * NKV * HD)      // 3072

#define ROPE_L2 0.10381025296522976f
#define SC 0.08838834764831845f             // 1/sqrt(128)
#define SCL2 (0.08838834764831845f * 1.4426950408889634f)

// -------------------- device scratch (all single fp16) --------------------
__device__ float2 g_rope[SEQ * 64];

__device__ __half g_xh[(size_t)MTOT * NE];
__device__ __half g_wh[(size_t)(NQKV + NE) * NE];   // Wq|Wk|Wv|Wo rows
__device__ __half g_yh[(size_t)MTOT * NE];

__device__ __half g_qh[(size_t)BATCH * NH * SEQ * HD];
__device__ __half g_kh[(size_t)BATCH * NKV * SEQ * HD];
__device__ __half g_vh[(size_t)BATCH * NKV * SEQ * HD];

// -------------------- PTX helpers (plain-target only) --------------------
__device__ __forceinline__ uint32_t cvta_smem(const void* p) {
    uint32_t a;
    asm("{ .reg .u64 t; cvta.to.shared.u64 t, %1; cvt.u32.u64 %0, t; }"
        : "=r"(a) : "l"(p));
    return a;
}
__device__ __forceinline__ void cp16(uint32_t dst, const void* src) {
    asm volatile("cp.async.cg.shared.global [%0], [%1], 16;" :: "r"(dst), "l"(src));
}
__device__ __forceinline__ void cp_commit() {
    asm volatile("cp.async.commit_group;" ::: "memory");
}
template <int N>
__device__ __forceinline__ void cp_wait() {
    asm volatile("cp.async.wait_group %0;" :: "n"(N) : "memory");
}
__device__ __forceinline__ void ldsm4(uint32_t& r0, uint32_t& r1,
                                      uint32_t& r2, uint32_t& r3, uint32_t a) {
    asm volatile("ldmatrix.sync.aligned.m8n8.x4.shared.b16 {%0,%1,%2,%3}, [%4];"
                 : "=r"(r0), "=r"(r1), "=r"(r2), "=r"(r3) : "r"(a));
}
__device__ __forceinline__ void ldsm4t(uint32_t& r0, uint32_t& r1,
                                       uint32_t& r2, uint32_t& r3, uint32_t a) {
    asm volatile("ldmatrix.sync.aligned.m8n8.x4.trans.shared.b16 {%0,%1,%2,%3}, [%4];"
                 : "=r"(r0), "=r"(r1), "=r"(r2), "=r"(r3) : "r"(a));
}
__device__ __forceinline__ void mma16816(float* c, const uint32_t* a,
                                         const uint32_t* b) {
    asm volatile(
        "mma.sync.aligned.m16n8k16.row.col.f32.f16.f16.f32 "
        "{%0,%1,%2,%3}, {%4,%5,%6,%7}, {%8,%9}, {%0,%1,%2,%3};"
        : "+f"(c[0]), "+f"(c[1]), "+f"(c[2]), "+f"(c[3])
        : "r"(a[0]), "r"(a[1]), "r"(a[2]), "r"(a[3]), "r"(b[0]), "r"(b[1]));
}

__device__ __forceinline__ uint32_t pack_h2(float a, float b) {
    __half2 h = __floats2half2_rn(a, b);
    return *(uint32_t*)&h;
}

// -------------------- merged prep kernel: rope table + fp32->fp16 ---------
#define N4X (MTOT * NE / 4)                 // 2097152
#define N4Q (NH * HD * NE / 4)              // 1048576
#define N4K (NKV * HD * NE / 4)             // 262144
#define N4ALL (N4X + 2 * N4Q + 2 * N4K)     // 4718592
#define ROPE_BLOCKS ((SEQ * 64) / 256)      // 512

__global__ void prep_kernel(const float* __restrict__ x,
                            const float* __restrict__ Wq,
                            const float* __restrict__ Wk,
                            const float* __restrict__ Wv,
                            const float* __restrict__ Wo,
                            const int* __restrict__ pos_ids)
{
    int bid = blockIdx.x;
    if (bid < ROPE_BLOCKS) {
        int idx = bid * 256 + threadIdx.x;
        int s = idx >> 6, p = idx & 63;
        float pos = (float)pos_ids[s];
        float f = pos * exp2f(-(float)(2 * p) * ROPE_L2);
        float sn, cs;
        sincosf(f, &sn, &cs);
        g_rope[idx] = make_float2(cs, sn);
        return;
    }
    int i = (bid - ROPE_BLOCKS) * 256 + threadIdx.x;
    if (i >= N4ALL) return;
    const float4* src;
    uint2* dst;
    if (i < N4X) {
        src = (const float4*)x + i;
        dst = (uint2*)g_xh + i;
    } else {
        int j = i - N4X;
        if (j < N4Q) {
            src = (const float4*)Wq + j;
        } else if (j < N4Q + N4K) {
            src = (const float4*)Wk + (j - N4Q);
        } else if (j < N4Q + 2 * N4K) {
            src = (const float4*)Wv + (j - N4Q - N4K);
        } else {
            src = (const float4*)Wo + (j - N4Q - 2 * N4K);
        }
        dst = (uint2*)g_wh + j;
    }
    float4 v = *src;
    *dst = make_uint2(pack_h2(v.x, v.y), pack_h2(v.z, v.w));
}

// ==========================================================================
// single-fp16 tensor-core GEMM (unchanged from round 9 — at pipe ceiling)
// ==========================================================================
#define KCH     64
#define NSTG    (NE / KCH)       // 32
#define ROWB    144              // 128B data + 16B pad
#define MATA    (128 * ROWB)     // 18432
#define STGB    (2 * MATA)       // 36864 per stage: A | B
#define NPIPE   3

template <int MODE>
__global__ __launch_bounds__(256, 2)
void gemm_kernel(int browbase, float* __restrict__ outp)
{
    extern __shared__ char smem[];
    const uint32_t sb = cvta_smem(smem);
    const int tid  = threadIdx.x;
    const int wid  = tid >> 5, lane = tid & 31;
    const int wm   = (wid >> 2) * 64;
    const int wn   = (wid & 3) * 32;
    const int bn   = blockIdx.x * 128;
    const int bm   = blockIdx.y * 128;

    const __half* A = (MODE == 0) ? g_xh : g_yh;

    float acc[4][4][4];
#pragma unroll
    for (int f = 0; f < 4; f++)
#pragma unroll
        for (int n = 0; n < 4; n++)
#pragma unroll
            for (int q = 0; q < 4; q++) acc[f][n][q] = 0.f;

    const int lrow = tid >> 3;
    const int lch  = tid & 7;

    const uint32_t aoff = (uint32_t)((wm + (lane & 15)) * ROWB + (lane >> 4) * 16);
    const uint32_t boff = (uint32_t)(MATA
        + (wn + (lane & 7) + ((lane >> 4) << 3)) * ROWB
        + ((lane >> 3) & 1) * 16);

    auto issue = [&](int s) {
        const uint32_t st = sb + (s % NPIPE) * STGB;
        const size_t ko = (size_t)s * KCH + lch * 8;
#pragma unroll
        for (int it = 0; it < 4; it++) {
            int r = lrow + it * 32;
            cp16(st + r * ROWB + lch * 16, A + (size_t)(bm + r) * NE + ko);
            cp16(st + MATA + r * ROWB + lch * 16,
                 g_wh + (size_t)(browbase + bn + r) * NE + ko);
        }
        cp_commit();
    };

    issue(0);
    issue(1);

    for (int s = 0; s < NSTG; s++) {
        if (s + 2 < NSTG) { issue(s + 2); cp_wait<2>(); }
        else if (s + 1 < NSTG) cp_wait<1>();
        else cp_wait<0>();
        __syncthreads();

        const uint32_t st = sb + (s % NPIPE) * STGB;
#pragma unroll
        for (int t = 0; t < 4; t++) {
            uint32_t bh[8];
#pragma unroll
            for (int g = 0; g < 2; g++)
                ldsm4(bh[g * 4 + 0], bh[g * 4 + 1], bh[g * 4 + 2], bh[g * 4 + 3],
                      st + boff + g * 16 * ROWB + t * 32);
#pragma unroll
            for (int f = 0; f < 4; f++) {
                uint32_t ah[4];
                ldsm4(ah[0], ah[1], ah[2], ah[3],
                      st + aoff + f * 16 * ROWB + t * 32);
#pragma unroll
                for (int n = 0; n < 4; n++)
                    mma16816(acc[f][n], ah, &bh[n * 2]);
            }
        }
        __syncthreads();
    }

    const int r0 = lane >> 2;
    const int c0 = (lane & 3) * 2;

    if (MODE == 1) {
#pragma unroll
        for (int f = 0; f < 4; f++)
#pragma unroll
            for (int n = 0; n < 4; n++) {
                int m = bm + wm + f * 16 + r0;
                int c = bn + wn + n * 8 + c0;
                *(float2*)&outp[(size_t)m * NE + c] =
                    make_float2(acc[f][n][0], acc[f][n][1]);
                *(float2*)&outp[(size_t)(m + 8) * NE + c] =
                    make_float2(acc[f][n][2], acc[f][n][3]);
            }
    } else {
        const int region = (bn < NH * HD) ? 0 : ((bn < NH * HD + NKV * HD) ? 1 : 2);
#pragma unroll
        for (int f = 0; f < 4; f++)
#pragma unroll
            for (int n = 0; n < 4; n++) {
                int nglob = bn + wn + n * 8 + c0;
#pragma unroll
                for (int half = 0; half < 2; half++) {
                    int m = bm + wm + f * 16 + r0 + half * 8;
                    int bb = m >> 11, s = m & (SEQ - 1);
                    float v0 = acc[f][n][half * 2 + 0];
                    float v1 = acc[f][n][half * 2 + 1];
                    if (region == 2) {
                        int nl = nglob - NH * HD - NKV * HD;
                        int h = nl >> 7, d0 = nl & 127;
                        size_t off = (((size_t)(bb * NKV + h)) * SEQ + s) * HD + d0;
                        *(uint32_t*)&g_vh[off] = pack_h2(v0, v1);
                    } else {
                        int nl = (region == 0) ? nglob : (nglob - NH * HD);
                        int h = nl >> 7, d0 = nl & 127;
                        float2 cs = g_rope[s * 64 + (d0 >> 1)];
                        float ox = v0 * cs.x - v1 * cs.y;
                        float oy = v1 * cs.x + v0 * cs.y;
                        if (region == 0) {
                            ox *= SCL2; oy *= SCL2;
                            size_t off = (((size_t)(bb * NH + h)) * SEQ + s) * HD + d0;
                            *(uint32_t*)&g_qh[off] = pack_h2(ox, oy);
                        } else {
                            size_t off = (((size_t)(bb * NKV + h)) * SEQ + s) * HD + d0;
                            *(uint32_t*)&g_kh[off] = pack_h2(ox, oy);
                        }
                    }
                }
            }
    }
}

// ==========================================================================
// Tensor-core flash attention, fp16 operands, fp32 accum, 128-KEY STAGES.
// CTA: 128 q-rows x (b,h). 8 warps. K/V tiles of 128 keys, double-buffered.
// Half the barriers/corrections/rescales per key vs 64-key stages.
// l (denominator) kept as per-thread partials; quad-reduced once at the end.
// ==========================================================================
#define AROW   272
#define QTB    (128 * AROW)             // 34816
#define KVM    (128 * AROW)             // 34816 per matrix (K or V)
#define KVSTG  (2 * KVM)                // 69632 per stage: K | V
#define ATT_SMEM (QTB + 2 * KVSTG)      // 174080 -> occupancy 1

__global__ void __launch_bounds__(256, 1)
attn_kernel(const int* __restrict__ pos_ids)
{
    extern __shared__ char smem[];
    const uint32_t sb = cvta_smem(smem);
    const int tid = threadIdx.x;
    const int lane = tid & 31, wq = tid >> 5;
    const int qt = gridDim.x - 1 - blockIdx.x;   // heavy tiles first
    const int bh = blockIdx.y;
    const int b = bh >> 4, h = bh & 15, kvh = h >> 2;
    const int q0 = qt * 128;

    const size_t qbase = (((size_t)(b * NH + h)) * SEQ + q0) * HD;
    const size_t kvbase = ((size_t)(b * NKV + kvh)) * SEQ * HD;

    // ---- load Q ----
#pragma unroll
    for (int it = 0; it < 8; it++) {
        int rem = it * 256 + tid;
        int row = rem >> 4, ch = rem & 15;
        cp16(sb + row * AROW + ch * 16,
             g_qh + qbase + (size_t)row * HD + ch * 8);
    }
    cp_commit();

    const int nkt = qt + 1;              // 128-key stages

    auto issue_kv = [&](int kt) {
        const uint32_t st = sb + QTB + (kt & 1) * KVSTG;
        const int k0 = kt * 128;
#pragma unroll
        for (int it = 0; it < 16; it++) {
            int mat = it >> 3;                 // 0 = K, 1 = V
            int rem = (it & 7) * 256 + tid;    // 0..2047
            int row = rem >> 4, ch = rem & 15;
            const __half* base = mat ? g_vh : g_kh;
            cp16(st + mat * KVM + row * AROW + ch * 16,
                 base + kvbase + (size_t)(k0 + row) * HD + ch * 8);
        }
        cp_commit();
    };

    issue_kv(0);

    float m_lo = -1e30f, m_hi = -1e30f, l_lo = 0.f, l_hi = 0.f;
    float o_acc[16][4];
#pragma unroll
    for (int nt = 0; nt < 16; nt++)
#pragma unroll
        for (int j = 0; j < 4; j++) o_acc[nt][j] = 0.f;

    const int r_lo = lane >> 2;
    const int pq_lo = pos_ids[q0 + 16 * wq + r_lo];
    const int pq_hi = pos_ids[q0 + 16 * wq + r_lo + 8];

    const uint32_t q_a = sb + (16 * wq + (lane & 15)) * AROW + (lane >> 4) * 16;
    const uint32_t k_row = (lane & 7) + ((lane >> 4) << 3);
    const uint32_t k_cb  = ((lane >> 3) & 1) * 16;
    const uint32_t v_row = (lane & 7) + (((lane >> 3) & 1) << 3);
    const uint32_t v_cb  = (lane >> 4) * 16;

    for (int kt = 0; kt < nkt; kt++) {
        if (kt + 1 < nkt) { issue_kv(kt + 1); cp_wait<1>(); }
        else cp_wait<0>();
        __syncthreads();
        const uint32_t st = sb + QTB + (kt & 1) * KVSTG;
        const int k0 = kt * 128;

        // ---- S = Q K^T (log2 domain), 128 keys -> s_acc[16][4] ----
        float s_acc[16][4];
#pragma unroll
        for (int nt = 0; nt < 16; nt++)
#pragma unroll
            for (int j = 0; j < 4; j++) s_acc[nt][j] = 0.f;

#pragma unroll
        for (int kc = 0; kc < 8; kc++) {
            uint32_t ah[4];
            ldsm4(ah[0], ah[1], ah[2], ah[3], q_a + kc * 32);
#pragma unroll
            for (int kp = 0; kp < 8; kp++) {
                uint32_t kh[4];
                ldsm4(kh[0], kh[1], kh[2], kh[3],
                      st + (16 * kp + k_row) * AROW + kc * 32 + k_cb);
                mma16816(s_acc[2 * kp],     ah, &kh[0]);
                mma16816(s_acc[2 * kp + 1], ah, &kh[2]);
            }
        }

        // ---- causal mask (only diagonal stage kt == qt can mask) ----
        if (k0 + 127 > pq_lo) {
#pragma unroll
            for (int nt = 0; nt < 16; nt++) {
                int c = k0 + 8 * nt + 2 * (lane & 3);
                if (c     > pq_lo) s_acc[nt][0] = -1e30f;
                if (c + 1 > pq_lo) s_acc[nt][1] = -1e30f;
                if (c     > pq_hi) s_acc[nt][2] = -1e30f;
                if (c + 1 > pq_hi) s_acc[nt][3] = -1e30f;
            }
        }

        // ---- online softmax (base-2), one correction per 128 keys ----
        float rm_lo = -1e30f, rm_hi = -1e30f;
#pragma unroll
        for (int nt = 0; nt < 16; nt++) {
            rm_lo = fmaxf(rm_lo, fmaxf(s_acc[nt][0], s_acc[nt][1]));
            rm_hi = fmaxf(rm_hi, fmaxf(s_acc[nt][2], s_acc[nt][3]));
        }
#pragma unroll
        for (int o = 1; o < 4; o <<= 1) {
            rm_lo = fmaxf(rm_lo, __shfl_xor_sync(0xffffffffu, rm_lo, o));
            rm_hi = fmaxf(rm_hi, __shfl_xor_sync(0xffffffffu, rm_hi, o));
        }
        bool need = (rm_lo > m_lo) || (rm_hi > m_hi);
        float nm_lo = fmaxf(m_lo, rm_lo), nm_hi = fmaxf(m_hi, rm_hi);
        float corr_lo = exp2f(m_lo - nm_lo), corr_hi = exp2f(m_hi - nm_hi);
        m_lo = nm_lo; m_hi = nm_hi;
        float rs_lo = 0.f, rs_hi = 0.f;
#pragma unroll
        for (int nt = 0; nt < 16; nt++) {
            s_acc[nt][0] = exp2f(s_acc[nt][0] - nm_lo);
            s_acc[nt][1] = exp2f(s_acc[nt][1] - nm_lo);
            s_acc[nt][2] = exp2f(s_acc[nt][2] - nm_hi);
            s_acc[nt][3] = exp2f(s_acc[nt][3] - nm_hi);
            rs_lo += s_acc[nt][0] + s_acc[nt][1];
            rs_hi += s_acc[nt][2] + s_acc[nt][3];
        }
        // per-thread partial l (quad-reduced once after the loop)
        l_lo = l_lo * corr_lo + rs_lo;
        l_hi = l_hi * corr_hi + rs_hi;
        if (__any_sync(0xffffffffu, need)) {
#pragma unroll
            for (int nt = 0; nt < 16; nt++) {
                o_acc[nt][0] *= corr_lo; o_acc[nt][1] *= corr_lo;
                o_acc[nt][2] *= corr_hi; o_acc[nt][3] *= corr_hi;
            }
        }

        // ---- O += P V (128 keys = 8 k16 chunks) ----
#pragma unroll
        for (int kc2 = 0; kc2 < 8; kc2++) {
            uint32_t p[4];
            p[0] = pack_h2(s_acc[2 * kc2][0],     s_acc[2 * kc2][1]);
            p[1] = pack_h2(s_acc[2 * kc2][2],     s_acc[2 * kc2][3]);
            p[2] = pack_h2(s_acc[2 * kc2 + 1][0], s_acc[2 * kc2 + 1][1]);
            p[3] = pack_h2(s_acc[2 * kc2 + 1][2], s_acc[2 * kc2 + 1][3]);
#pragma unroll
            for (int nd = 0; nd < 8; nd++) {
                uint32_t vh[4];
                ldsm4t(vh[0], vh[1], vh[2], vh[3],
                       st + KVM + (16 * kc2 + v_row) * AROW + nd * 32 + v_cb);
                mma16816(o_acc[2 * nd],     p, &vh[0]);
                mma16816(o_acc[2 * nd + 1], p, &vh[2]);
            }
        }
        __syncthreads();
    }

    // ---- final l reduction across the quad, then normalize + store ----
#pragma unroll
    for (int o = 1; o < 4; o <<= 1) {
        l_lo += __shfl_xor_sync(0xffffffffu, l_lo, o);
        l_hi += __shfl_xor_sync(0xffffffffu, l_hi, o);
    }
    float inv_lo = 1.0f / l_lo, inv_hi = 1.0f / l_hi;
    int row_lo = q0 + 16 * wq + r_lo;
#pragma unroll
    for (int nt = 0; nt < 16; nt++) {
        int col = h * HD + 8 * nt + 2 * (lane & 3);
        size_t off_lo = (size_t)(b * SEQ + row_lo) * NE + col;
        size_t off_hi = (size_t)(b * SEQ + row_lo + 8) * NE + col;
        *(uint32_t*)&g_yh[off_lo] = pack_h2(o_acc[nt][0] * inv_lo, o_acc[nt][1] * inv_lo);
        *(uint32_t*)&g_yh[off_hi] = pack_h2(o_acc[nt][2] * inv_hi, o_acc[nt][3] * inv_hi);
    }
}

// ==========================================================================
extern "C" void kernel_launch(void* const* d_in, const int* in_sizes, int n_in,
                              void* d_out, int out_size)
{
    const float* x   = (const float*)d_in[0];
    const float* Wq  = (const float*)d_in[1];
    const float* Wk  = (const float*)d_in[2];
    const float* Wv  = (const float*)d_in[3];
    const float* Wo  = (const float*)d_in[4];
    const int*   pos = (const int*)d_in[5];
    float* out = (float*)d_out;

    // rope table + fp16 conversions, one launch
    prep_kernel<<<ROPE_BLOCKS + (N4ALL + 255) / 256, 256>>>(x, Wq, Wk, Wv, Wo, pos);

    const int gsmem = NPIPE * STGB;   // 110592 -> occupancy 2
    cudaFuncSetAttribute(gemm_kernel<0>,
                         cudaFuncAttributeMaxDynamicSharedMemorySize, gsmem);
    cudaFuncSetAttribute(gemm_kernel<1>,
                         cudaFuncAttributeMaxDynamicSharedMemorySize, gsmem);

    // QKV projection: N = 3072 -> 24 tiles of 128; M = 4096 -> 32 tiles
    gemm_kernel<0><<<dim3(24, 32), 256, gsmem>>>(0, nullptr);

    // attention (tensor-core, fp16, 128-key stages)
    cudaFuncSetAttribute(attn_kernel,
                         cudaFuncAttributeMaxDynamicSharedMemorySize, ATT_SMEM);
    attn_kernel<<<dim3(SEQ / 128, BATCH * NH), 256, ATT_SMEM>>>(pos);

    // output projection: N = 2048 -> 16 tiles of 128; M = 4096 -> 32 tiles
    gemm_kernel<1><<<dim3(16, 32), 256, gsmem>>>(NQKV, out);
}